// round 3
// baseline (speedup 1.0000x reference)
#include <cuda_runtime.h>
#include <cuda_bf16.h>
#include <cstdint>

// Problem constants
#define BB 4
#define TT 2048
#define CC 1024
#define HH 16
#define DD 64
#define MM (BB*TT)   // 8192

// ---------------------------------------------------------------------------
// Scratch (device globals: allocation-free)
// ---------------------------------------------------------------------------
__device__ float g_q[(size_t)BB*HH*TT*DD];   // [B,H,T,D]
__device__ float g_k[(size_t)BB*HH*TT*DD];
__device__ float g_v[(size_t)BB*HH*TT*DD];
__device__ float g_y[(size_t)MM*CC];         // attention out, [B,T,C]

__device__ __nv_bfloat16 g_xhi[(size_t)MM*CC];
__device__ __nv_bfloat16 g_xlo[(size_t)MM*CC];
__device__ __nv_bfloat16 g_whi[(size_t)4*CC*CC];   // q,k,v,p packed
__device__ __nv_bfloat16 g_wlo[(size_t)4*CC*CC];
__device__ __nv_bfloat16 g_yhi[(size_t)MM*CC];
__device__ __nv_bfloat16 g_ylo[(size_t)MM*CC];

// ---------------------------------------------------------------------------
// mma.sync helpers (sm_80+ path; runs on tensor pipe as HMMA on sm_103)
// ---------------------------------------------------------------------------
__device__ __forceinline__ uint32_t smem_u32(const void* p) {
    uint32_t a;
    asm("{ .reg .u64 t; cvta.to.shared.u64 t, %1; cvt.u32.u64 %0, t; }"
        : "=r"(a) : "l"(p));
    return a;
}

__device__ __forceinline__ void ldsm4(uint32_t* r, uint32_t addr) {
    asm volatile("ldmatrix.sync.aligned.m8n8.x4.shared.b16 {%0,%1,%2,%3}, [%4];"
        : "=r"(r[0]), "=r"(r[1]), "=r"(r[2]), "=r"(r[3]) : "r"(addr));
}
__device__ __forceinline__ void ldsm2(uint32_t* r, uint32_t addr) {
    asm volatile("ldmatrix.sync.aligned.m8n8.x2.shared.b16 {%0,%1}, [%2];"
        : "=r"(r[0]), "=r"(r[1]) : "r"(addr));
}

__device__ __forceinline__ void mma16816(float* d, const uint32_t* a, const uint32_t* b) {
    asm volatile(
        "mma.sync.aligned.m16n8k16.row.col.f32.bf16.bf16.f32 "
        "{%0,%1,%2,%3}, {%4,%5,%6,%7}, {%8,%9}, {%0,%1,%2,%3};"
        : "+f"(d[0]), "+f"(d[1]), "+f"(d[2]), "+f"(d[3])
        : "r"(a[0]), "r"(a[1]), "r"(a[2]), "r"(a[3]), "r"(b[0]), "r"(b[1]));
}

// ---------------------------------------------------------------------------
// Conversion kernels (fp32 -> bf16 hi + bf16 lo residual)
// ---------------------------------------------------------------------------
__global__ void cvt_x(const float* __restrict__ src) {
    int i = blockIdx.x * blockDim.x + threadIdx.x;
    if (i < MM * CC) {
        float v = src[i];
        __nv_bfloat16 h = __float2bfloat16(v);
        g_xhi[i] = h;
        g_xlo[i] = __float2bfloat16(v - __bfloat162float(h));
    }
}
__global__ void cvt_w(const float* __restrict__ src, int which) {
    int i = blockIdx.x * blockDim.x + threadIdx.x;
    if (i < CC * CC) {
        float v = src[i];
        __nv_bfloat16 h = __float2bfloat16(v);
        g_whi[(size_t)which * CC * CC + i] = h;
        g_wlo[(size_t)which * CC * CC + i] = __float2bfloat16(v - __bfloat162float(h));
    }
}
__global__ void cvt_y() {
    int i = blockIdx.x * blockDim.x + threadIdx.x;
    if (i < MM * CC) {
        float v = g_y[i];
        __nv_bfloat16 h = __float2bfloat16(v);
        g_yhi[i] = h;
        g_ylo[i] = __float2bfloat16(v - __bfloat162float(h));
    }
}

// ---------------------------------------------------------------------------
// Tensor-core GEMM: C[128x128] = A[m0:,:1024] * W[n0:,:1024]^T  via
// bf16 hi/lo 3-term emulation on mma.sync m16n8k16.
// 512 threads = 16 warps, warp tile 64x16 (wm=wid>>3, wn=wid&7).
// Smem: 4 staging tiles 128 rows x 32 bf16, row stride 40 (LDSM conflict-free).
// ---------------------------------------------------------------------------
#define ASTR 40

struct GemmAcc { float a[4][2][4]; };   // [mfrag][nfrag][quad]

__device__ __forceinline__ void gemm_mma_body(
    const __nv_bfloat16* __restrict__ Ahi, const __nv_bfloat16* __restrict__ Alo,
    const __nv_bfloat16* __restrict__ Whi, const __nv_bfloat16* __restrict__ Wlo,
    int m0, int n0, GemmAcc& acc)
{
    __shared__ __nv_bfloat16 sAh[128 * ASTR];
    __shared__ __nv_bfloat16 sAl[128 * ASTR];
    __shared__ __nv_bfloat16 sBh[128 * ASTR];
    __shared__ __nv_bfloat16 sBl[128 * ASTR];

    const int tid = threadIdx.x;
    const int wid = tid >> 5;
    const int l   = tid & 31;
    const int wm  = wid >> 3;     // 0..1  -> m offset 64*wm
    const int wn  = wid & 7;      // 0..7  -> n offset 16*wn

    const uint32_t bAh = smem_u32(sAh);
    const uint32_t bAl = smem_u32(sAl);
    const uint32_t bBh = smem_u32(sBh);
    const uint32_t bBl = smem_u32(sBl);

    #pragma unroll
    for (int mf = 0; mf < 4; mf++)
        #pragma unroll
        for (int nf = 0; nf < 2; nf++)
            #pragma unroll
            for (int q = 0; q < 4; q++) acc.a[mf][nf][q] = 0.f;

    // per-thread staging coords: 512 threads x 16B = one 128x32 bf16 tile
    const int sr = tid >> 2;            // 0..127
    const int sc = (tid & 3) * 8;       // 0,8,16,24

    // ldmatrix per-lane address offsets
    const int a_row = (l & 15);
    const int a_kad = ((l >> 4) << 3);
    const int b_row = (l & 7);
    const int b_kad = (((l >> 3) & 1) << 3);

    #pragma unroll 1
    for (int k0 = 0; k0 < CC; k0 += 32) {
        __syncthreads();
        *(uint4*)&sAh[sr * ASTR + sc] = *(const uint4*)(Ahi + (size_t)(m0 + sr) * CC + k0 + sc);
        *(uint4*)&sAl[sr * ASTR + sc] = *(const uint4*)(Alo + (size_t)(m0 + sr) * CC + k0 + sc);
        *(uint4*)&sBh[sr * ASTR + sc] = *(const uint4*)(Whi + (size_t)(n0 + sr) * CC + k0 + sc);
        *(uint4*)&sBl[sr * ASTR + sc] = *(const uint4*)(Wlo + (size_t)(n0 + sr) * CC + k0 + sc);
        __syncthreads();

        #pragma unroll
        for (int ks = 0; ks < 32; ks += 16) {
            uint32_t ah[4][4], bh[2][2], bl[2][2], al[4][4];
            #pragma unroll
            for (int mf = 0; mf < 4; mf++) {
                uint32_t off = (uint32_t)((wm * 64 + mf * 16 + a_row) * ASTR + ks + a_kad) * 2;
                ldsm4(ah[mf], bAh + off);
            }
            #pragma unroll
            for (int nf = 0; nf < 2; nf++) {
                uint32_t off = (uint32_t)((wn * 16 + nf * 8 + b_row) * ASTR + ks + b_kad) * 2;
                ldsm2(bh[nf], bBh + off);
                ldsm2(bl[nf], bBl + off);
            }
            // hi*hi and hi*lo
            #pragma unroll
            for (int mf = 0; mf < 4; mf++)
                #pragma unroll
                for (int nf = 0; nf < 2; nf++) {
                    mma16816(acc.a[mf][nf], ah[mf], bh[nf]);
                    mma16816(acc.a[mf][nf], ah[mf], bl[nf]);
                }
            // lo*hi
            #pragma unroll
            for (int mf = 0; mf < 4; mf++) {
                uint32_t off = (uint32_t)((wm * 64 + mf * 16 + a_row) * ASTR + ks + a_kad) * 2;
                ldsm4(al[mf], bAl + off);
            }
            #pragma unroll
            for (int mf = 0; mf < 4; mf++)
                #pragma unroll
                for (int nf = 0; nf < 2; nf++)
                    mma16816(acc.a[mf][nf], al[mf], bh[nf]);
        }
    }
}

// QKV projection: grid (8, 64, 3); scatter into [B,H,T,D]
__global__ __launch_bounds__(512, 1)
void mma_qkv() {
    const int which = blockIdx.z;
    const int m0 = blockIdx.y * 128;
    const int n0 = blockIdx.x * 128;
    const __nv_bfloat16* Wh = g_whi + (size_t)which * CC * CC;
    const __nv_bfloat16* Wl = g_wlo + (size_t)which * CC * CC;
    float* dst = (which == 0) ? g_q : (which == 1) ? g_k : g_v;

    GemmAcc acc;
    gemm_mma_body(g_xhi, g_xlo, Wh, Wl, m0, n0, acc);

    const int wid = threadIdx.x >> 5;
    const int l   = threadIdx.x & 31;
    const int wm  = wid >> 3;
    const int wn  = wid & 7;

    #pragma unroll
    for (int mf = 0; mf < 4; mf++) {
        #pragma unroll
        for (int nf = 0; nf < 2; nf++) {
            int col = n0 + wn * 16 + nf * 8 + (l & 3) * 2;
            int h = col >> 6, d = col & 63;
            #pragma unroll
            for (int half = 0; half < 2; half++) {
                int m = m0 + wm * 64 + mf * 16 + (l >> 2) + half * 8;
                int b = m >> 11, t = m & (TT - 1);
                *(float2*)&dst[(((size_t)(b * HH + h) * TT + t) << 6) + d] =
                    make_float2(acc.a[mf][nf][half*2 + 0], acc.a[mf][nf][half*2 + 1]);
            }
        }
    }
}

// Output projection: grid (8, 64); row-major out
__global__ __launch_bounds__(512, 1)
void mma_proj(float* __restrict__ out) {
    const int m0 = blockIdx.y * 128;
    const int n0 = blockIdx.x * 128;
    const __nv_bfloat16* Wh = g_whi + (size_t)3 * CC * CC;
    const __nv_bfloat16* Wl = g_wlo + (size_t)3 * CC * CC;

    GemmAcc acc;
    gemm_mma_body(g_yhi, g_ylo, Wh, Wl, m0, n0, acc);

    const int wid = threadIdx.x >> 5;
    const int l   = threadIdx.x & 31;
    const int wm  = wid >> 3;
    const int wn  = wid & 7;

    #pragma unroll
    for (int mf = 0; mf < 4; mf++) {
        #pragma unroll
        for (int nf = 0; nf < 2; nf++) {
            int col = n0 + wn * 16 + nf * 8 + (l & 3) * 2;
            #pragma unroll
            for (int half = 0; half < 2; half++) {
                int m = m0 + wm * 64 + mf * 16 + (l >> 2) + half * 8;
                *(float2*)&out[(size_t)m * CC + col] =
                    make_float2(acc.a[mf][nf][half*2 + 0], acc.a[mf][nf][half*2 + 1]);
            }
        }
    }
}

// ---------------------------------------------------------------------------
// fp32 flash attention (unchanged; known correct). grid (T/64, B*H), 256 thr.
// ---------------------------------------------------------------------------
__global__ __launch_bounds__(256)
void flash_kernel()
{
    __shared__ float Qs[64][68];
    __shared__ float Ks[32][68];
    __shared__ float Vs[32][68];
    __shared__ float Ps[64][36];

    const int tid = threadIdx.x;
    const int tx  = tid & 15;
    const int ty  = tid >> 4;
    const int qt  = blockIdx.x;
    const int bh  = blockIdx.y;
    const int b   = bh >> 4;
    const int h   = bh & 15;
    const size_t base = (size_t)bh * TT * DD;

    {
        const float4* src = (const float4*)(g_q + base + (size_t)qt * 64 * DD);
        #pragma unroll
        for (int it = 0; it < 4; it++) {
            int f  = tid + it * 256;
            int r  = f >> 4;
            int c4 = f & 15;
            *(float4*)&Qs[r][c4*4] = src[f];
        }
    }

    float o[4][4];
    float mi[4], li[4];
    #pragma unroll
    for (int i = 0; i < 4; i++) {
        mi[i] = -1e30f; li[i] = 0.f;
        #pragma unroll
        for (int j = 0; j < 4; j++) o[i][j] = 0.f;
    }

    const int ntile = 2*qt + 2;
    const int qbase = qt * 64;

    for (int jt = 0; jt < ntile; jt++) {
        __syncthreads();
        {
            const float4* ks = (const float4*)(g_k + base + (size_t)jt * 32 * DD);
            const float4* vs = (const float4*)(g_v + base + (size_t)jt * 32 * DD);
            #pragma unroll
            for (int it = 0; it < 2; it++) {
                int f  = tid + it * 256;
                int r  = f >> 4;
                int c4 = f & 15;
                *(float4*)&Ks[r][c4*4] = ks[f];
                *(float4*)&Vs[r][c4*4] = vs[f];
            }
        }
        __syncthreads();

        float s0[4], s1[4];
        #pragma unroll
        for (int i = 0; i < 4; i++) { s0[i] = 0.f; s1[i] = 0.f; }
        #pragma unroll
        for (int d4 = 0; d4 < 16; d4++) {
            float4 kv0 = *(const float4*)&Ks[tx*2 + 0][d4*4];
            float4 kv1 = *(const float4*)&Ks[tx*2 + 1][d4*4];
            #pragma unroll
            for (int i = 0; i < 4; i++) {
                float4 qv = *(const float4*)&Qs[ty*4 + i][d4*4];
                s0[i] += qv.x*kv0.x + qv.y*kv0.y + qv.z*kv0.z + qv.w*kv0.w;
                s1[i] += qv.x*kv1.x + qv.y*kv1.y + qv.z*kv1.z + qv.w*kv1.w;
            }
        }

        const int kbase = jt * 32;
        const int kg0 = kbase + tx*2;
        const int kg1 = kg0 + 1;
        #pragma unroll
        for (int i = 0; i < 4; i++) {
            int qg = qbase + ty*4 + i;
            float v0 = s0[i] * 0.125f;
            float v1 = s1[i] * 0.125f;
            if (kg0 > qg) v0 = -1e30f;
            if (kg1 > qg) v1 = -1e30f;
            float rm = fmaxf(v0, v1);
            rm = fmaxf(rm, __shfl_xor_sync(0xffffffffu, rm, 8));
            rm = fmaxf(rm, __shfl_xor_sync(0xffffffffu, rm, 4));
            rm = fmaxf(rm, __shfl_xor_sync(0xffffffffu, rm, 2));
            rm = fmaxf(rm, __shfl_xor_sync(0xffffffffu, rm, 1));
            float mnew = fmaxf(mi[i], rm);
            float corr = __expf(mi[i] - mnew);
            float p0 = __expf(v0 - mnew);
            float p1 = __expf(v1 - mnew);
            float rs = p0 + p1;
            rs += __shfl_xor_sync(0xffffffffu, rs, 8);
            rs += __shfl_xor_sync(0xffffffffu, rs, 4);
            rs += __shfl_xor_sync(0xffffffffu, rs, 2);
            rs += __shfl_xor_sync(0xffffffffu, rs, 1);
            li[i] = li[i]*corr + rs;
            mi[i] = mnew;
            #pragma unroll
            for (int j = 0; j < 4; j++) o[i][j] *= corr;
            Ps[ty*4 + i][tx*2 + 0] = p0;
            Ps[ty*4 + i][tx*2 + 1] = p1;
        }
        __syncthreads();

        #pragma unroll 4
        for (int c = 0; c < 32; c++) {
            float4 vv = *(const float4*)&Vs[c][tx*4];
            #pragma unroll
            for (int i = 0; i < 4; i++) {
                float pp = Ps[ty*4 + i][c];
                o[i][0] += pp * vv.x;
                o[i][1] += pp * vv.y;
                o[i][2] += pp * vv.z;
                o[i][3] += pp * vv.w;
            }
        }
    }

    #pragma unroll
    for (int i = 0; i < 4; i++) {
        float inv = 1.f / li[i];
        int t = qbase + ty*4 + i;
        float4 v = make_float4(o[i][0]*inv, o[i][1]*inv, o[i][2]*inv, o[i][3]*inv);
        *(float4*)&g_y[(((size_t)(b*TT + t)) << 10) + h*64 + tx*4] = v;
    }
}

// ---------------------------------------------------------------------------
extern "C" void kernel_launch(void* const* d_in, const int* in_sizes, int n_in,
                              void* d_out, int out_size)
{
    const float* x  = (const float*)d_in[0];
    const float* Wq = (const float*)d_in[1];
    const float* Wk = (const float*)d_in[2];
    const float* Wv = (const float*)d_in[3];
    const float* Wp = (const float*)d_in[4];
    float* out = (float*)d_out;

    cvt_x<<<(MM*CC + 255)/256, 256>>>(x);
    cvt_w<<<(CC*CC + 255)/256, 256>>>(Wq, 0);
    cvt_w<<<(CC*CC + 255)/256, 256>>>(Wk, 1);
    cvt_w<<<(CC*CC + 255)/256, 256>>>(Wv, 2);
    cvt_w<<<(CC*CC + 255)/256, 256>>>(Wp, 3);

    mma_qkv<<<dim3(CC/128, MM/128, 3), 512>>>();
    flash_kernel<<<dim3(TT/64, BB*HH), 256>>>();
    cvt_y<<<(MM*CC + 255)/256, 256>>>();
    mma_proj<<<dim3(CC/128, MM/128), 512>>>(out);
}

// round 4
// speedup vs baseline: 3.5006x; 3.5006x over previous
#include <cuda_runtime.h>
#include <cuda_bf16.h>
#include <cuda_fp16.h>
#include <cstdint>

#define BB 4
#define TT 2048
#define CC 1024
#define HH 16
#define DD 64
#define MM (BB*TT)   // 8192

// ---------------------------------------------------------------------------
// Scratch (device globals, 16B aligned for vector/cp.async access)
// ---------------------------------------------------------------------------
__device__ __align__(16) __nv_bfloat16 g_xhi[(size_t)MM*CC];
__device__ __align__(16) __nv_bfloat16 g_xlo[(size_t)MM*CC];
__device__ __align__(16) __nv_bfloat16 g_whi[(size_t)4*CC*CC];
__device__ __align__(16) __nv_bfloat16 g_wlo[(size_t)4*CC*CC];
__device__ __align__(16) __half g_qh[(size_t)MM*CC];   // [B,H,T,D] (B*H*T*D == MM*CC)
__device__ __align__(16) __half g_ql[(size_t)MM*CC];
__device__ __align__(16) __half g_kh[(size_t)MM*CC];
__device__ __align__(16) __half g_kl[(size_t)MM*CC];
__device__ __align__(16) __half g_vh[(size_t)MM*CC];
__device__ __align__(16) __half g_vl[(size_t)MM*CC];
__device__ __align__(16) __nv_bfloat16 g_yhi[(size_t)MM*CC];  // [B,T,C]
__device__ __align__(16) __nv_bfloat16 g_ylo[(size_t)MM*CC];

// ---------------------------------------------------------------------------
// PTX helpers
// ---------------------------------------------------------------------------
__device__ __forceinline__ uint32_t smem_u32(const void* p) {
    uint32_t a;
    asm("{ .reg .u64 t; cvta.to.shared.u64 t, %1; cvt.u32.u64 %0, t; }"
        : "=r"(a) : "l"(p));
    return a;
}
__device__ __forceinline__ void cp16(uint32_t dst, const void* src) {
    asm volatile("cp.async.cg.shared.global [%0], [%1], 16;" :: "r"(dst), "l"(src));
}
__device__ __forceinline__ void cp_commit() {
    asm volatile("cp.async.commit_group;" ::: "memory");
}
template<int N> __device__ __forceinline__ void cp_wait() {
    asm volatile("cp.async.wait_group %0;" :: "n"(N) : "memory");
}
__device__ __forceinline__ void ldsm4(uint32_t* r, uint32_t a) {
    asm volatile("ldmatrix.sync.aligned.m8n8.x4.shared.b16 {%0,%1,%2,%3}, [%4];"
        : "=r"(r[0]), "=r"(r[1]), "=r"(r[2]), "=r"(r[3]) : "r"(a));
}
__device__ __forceinline__ void ldsm4t(uint32_t* r, uint32_t a) {
    asm volatile("ldmatrix.sync.aligned.m8n8.x4.trans.shared.b16 {%0,%1,%2,%3}, [%4];"
        : "=r"(r[0]), "=r"(r[1]), "=r"(r[2]), "=r"(r[3]) : "r"(a));
}
__device__ __forceinline__ void mma_bf16(float* d, const uint32_t* a, uint32_t b0, uint32_t b1) {
    asm volatile(
        "mma.sync.aligned.m16n8k16.row.col.f32.bf16.bf16.f32 "
        "{%0,%1,%2,%3}, {%4,%5,%6,%7}, {%8,%9}, {%0,%1,%2,%3};"
        : "+f"(d[0]), "+f"(d[1]), "+f"(d[2]), "+f"(d[3])
        : "r"(a[0]), "r"(a[1]), "r"(a[2]), "r"(a[3]), "r"(b0), "r"(b1));
}
__device__ __forceinline__ void mma_f16(float* d, const uint32_t* a, uint32_t b0, uint32_t b1) {
    asm volatile(
        "mma.sync.aligned.m16n8k16.row.col.f32.f16.f16.f32 "
        "{%0,%1,%2,%3}, {%4,%5,%6,%7}, {%8,%9}, {%0,%1,%2,%3};"
        : "+f"(d[0]), "+f"(d[1]), "+f"(d[2]), "+f"(d[3])
        : "r"(a[0]), "r"(a[1]), "r"(a[2]), "r"(a[3]), "r"(b0), "r"(b1));
}
__device__ __forceinline__ uint32_t packh2(__half a, __half b) {
    __half2 h = __halves2half2(a, b);
    return *(uint32_t*)&h;
}

// ---------------------------------------------------------------------------
// Conversion kernels (fp32 -> bf16 hi + lo residual)
// ---------------------------------------------------------------------------
__global__ void cvt_x(const float* __restrict__ src) {
    int i = blockIdx.x * blockDim.x + threadIdx.x;
    if (i < MM * CC) {
        float v = src[i];
        __nv_bfloat16 h = __float2bfloat16(v);
        g_xhi[i] = h;
        g_xlo[i] = __float2bfloat16(v - __bfloat162float(h));
    }
}
__global__ void cvt_w(const float* __restrict__ src, int which) {
    int i = blockIdx.x * blockDim.x + threadIdx.x;
    if (i < CC * CC) {
        float v = src[i];
        __nv_bfloat16 h = __float2bfloat16(v);
        g_whi[(size_t)which * CC * CC + i] = h;
        g_wlo[(size_t)which * CC * CC + i] = __float2bfloat16(v - __bfloat162float(h));
    }
}

// ---------------------------------------------------------------------------
// GEMM: C[128x128] = A * W^T, bf16 3-term hi/lo, cp.async 2-stage pipeline.
// 256 threads, 8 warps (2m x 4n), warp tile 64x32.
// smem: 2 stages x 4 tiles (Ah,Al,Bh,Bl) of 128x32 bf16, row stride 40.
// ---------------------------------------------------------------------------
#define GSTR 40
#define GT_ELEMS (128*GSTR)          // 5120 elems per tile
#define GSTAGE_B (4*GT_ELEMS*2)      // 40960 bytes per stage
#define GSMEM (2*GSTAGE_B)           // 81920

__device__ __forceinline__ void gemm_issue(
    uint32_t sb, int stage,
    const __nv_bfloat16* __restrict__ Ah, const __nv_bfloat16* __restrict__ Al,
    const __nv_bfloat16* __restrict__ Bh, const __nv_bfloat16* __restrict__ Bl,
    int m0, int n0, int k0)
{
    const int t = threadIdx.x;
    const uint32_t stb = sb + stage * GSTAGE_B;
    #pragma unroll
    for (int i = 0; i < 8; i++) {
        const int tile = i >> 1;
        int rem = ((i & 1) << 8) | t;
        int row = rem >> 2;
        int c16 = rem & 3;
        const __nv_bfloat16* src;
        if      (tile == 0) src = Ah + (size_t)(m0 + row) * CC + k0 + c16 * 8;
        else if (tile == 1) src = Al + (size_t)(m0 + row) * CC + k0 + c16 * 8;
        else if (tile == 2) src = Bh + (size_t)(n0 + row) * CC + k0 + c16 * 8;
        else                src = Bl + (size_t)(n0 + row) * CC + k0 + c16 * 8;
        cp16(stb + (uint32_t)(tile * GT_ELEMS + row * GSTR + c16 * 8) * 2, src);
    }
}

__device__ __forceinline__ void gemm_body(
    const __nv_bfloat16* __restrict__ Ah, const __nv_bfloat16* __restrict__ Al,
    const __nv_bfloat16* __restrict__ Bh, const __nv_bfloat16* __restrict__ Bl,
    int m0, int n0, uint32_t sb, float acc[4][4][4])
{
    const int l  = threadIdx.x & 31;
    const int wid = threadIdx.x >> 5;
    const int wm = wid >> 2;
    const int wn = wid & 3;

    #pragma unroll
    for (int mf = 0; mf < 4; mf++)
        #pragma unroll
        for (int nf = 0; nf < 4; nf++)
            #pragma unroll
            for (int q = 0; q < 4; q++) acc[mf][nf][q] = 0.f;

    gemm_issue(sb, 0, Ah, Al, Bh, Bl, m0, n0, 0);
    cp_commit();

    #pragma unroll 1
    for (int c = 0; c < 32; c++) {
        if (c + 1 < 32) {
            gemm_issue(sb, (c + 1) & 1, Ah, Al, Bh, Bl, m0, n0, (c + 1) * 32);
            cp_commit();
            cp_wait<1>();
        } else {
            cp_wait<0>();
        }
        __syncthreads();

        const uint32_t stb = sb + (c & 1) * GSTAGE_B;
        const uint32_t tAh = stb;
        const uint32_t tAl = stb + GT_ELEMS * 2;
        const uint32_t tBh = stb + 2 * GT_ELEMS * 2;
        const uint32_t tBl = stb + 3 * GT_ELEMS * 2;
        const uint32_t lrow = (l & 15);
        const uint32_t lkad = ((l >> 4) << 3);

        #pragma unroll
        for (int ks = 0; ks < 32; ks += 16) {
            uint32_t ah[4][4], al[4][4];
            #pragma unroll
            for (int mf = 0; mf < 4; mf++) {
                uint32_t off = (uint32_t)((wm * 64 + mf * 16 + lrow) * GSTR + ks + lkad) * 2;
                ldsm4(ah[mf], tAh + off);
                ldsm4(al[mf], tAl + off);
            }
            uint32_t bh[4][2], bl[4][2];
            #pragma unroll
            for (int p = 0; p < 2; p++) {
                uint32_t off = (uint32_t)((wn * 32 + p * 16 + lrow) * GSTR + ks + lkad) * 2;
                uint32_t r[4], rl[4];
                ldsm4(r,  tBh + off);
                ldsm4(rl, tBl + off);
                bh[2*p][0]   = r[0]; bh[2*p][1]   = r[2];
                bh[2*p+1][0] = r[1]; bh[2*p+1][1] = r[3];
                bl[2*p][0]   = rl[0]; bl[2*p][1]   = rl[2];
                bl[2*p+1][0] = rl[1]; bl[2*p+1][1] = rl[3];
            }
            #pragma unroll
            for (int mf = 0; mf < 4; mf++)
                #pragma unroll
                for (int nf = 0; nf < 4; nf++) {
                    mma_bf16(acc[mf][nf], ah[mf], bh[nf][0], bh[nf][1]);
                    mma_bf16(acc[mf][nf], ah[mf], bl[nf][0], bl[nf][1]);
                    mma_bf16(acc[mf][nf], al[mf], bh[nf][0], bh[nf][1]);
                }
        }
        __syncthreads();
    }
}

// QKV projection: grid (8, 64, 3); writes fp16 hi/lo into [B,H,T,D]
__global__ __launch_bounds__(256, 2)
void gemm_qkv() {
    extern __shared__ __align__(16) char gsm[];
    const uint32_t sb = smem_u32(gsm);
    const int which = blockIdx.z;
    const int m0 = blockIdx.y * 128;
    const int n0 = blockIdx.x * 128;
    const __nv_bfloat16* Wh = g_whi + (size_t)which * CC * CC;
    const __nv_bfloat16* Wl = g_wlo + (size_t)which * CC * CC;

    float acc[4][4][4];
    gemm_body(g_xhi, g_xlo, Wh, Wl, m0, n0, sb, acc);

    __half* dh = (which == 0) ? g_qh : (which == 1) ? g_kh : g_vh;
    __half* dl = (which == 0) ? g_ql : (which == 1) ? g_kl : g_vl;

    const int l  = threadIdx.x & 31;
    const int wid = threadIdx.x >> 5;
    const int wm = wid >> 2, wn = wid & 3;

    #pragma unroll
    for (int mf = 0; mf < 4; mf++) {
        #pragma unroll
        for (int nf = 0; nf < 4; nf++) {
            int col = n0 + wn * 32 + nf * 8 + (l & 3) * 2;
            int hh = col >> 6, d = col & 63;
            #pragma unroll
            for (int hf = 0; hf < 2; hf++) {
                int m = m0 + wm * 64 + mf * 16 + (l >> 2) + hf * 8;
                int b = m >> 11, t = m & (TT - 1);
                size_t idx = (((size_t)(b * HH + hh) * TT + t) << 6) + d;
                float f0 = acc[mf][nf][hf*2 + 0];
                float f1 = acc[mf][nf][hf*2 + 1];
                __half h0 = __float2half_rn(f0), h1 = __float2half_rn(f1);
                __half e0 = __float2half_rn(f0 - __half2float(h0));
                __half e1 = __float2half_rn(f1 - __half2float(h1));
                *(__half2*)&dh[idx] = __halves2half2(h0, h1);
                *(__half2*)&dl[idx] = __halves2half2(e0, e1);
            }
        }
    }
}

// Output projection: grid (8, 64); fp32 out
__global__ __launch_bounds__(256, 2)
void gemm_proj(float* __restrict__ out) {
    extern __shared__ __align__(16) char gsm[];
    const uint32_t sb = smem_u32(gsm);
    const int m0 = blockIdx.y * 128;
    const int n0 = blockIdx.x * 128;
    const __nv_bfloat16* Wh = g_whi + (size_t)3 * CC * CC;
    const __nv_bfloat16* Wl = g_wlo + (size_t)3 * CC * CC;

    float acc[4][4][4];
    gemm_body(g_yhi, g_ylo, Wh, Wl, m0, n0, sb, acc);

    const int l  = threadIdx.x & 31;
    const int wid = threadIdx.x >> 5;
    const int wm = wid >> 2, wn = wid & 3;

    #pragma unroll
    for (int mf = 0; mf < 4; mf++)
        #pragma unroll
        for (int nf = 0; nf < 4; nf++) {
            int col = n0 + wn * 32 + nf * 8 + (l & 3) * 2;
            #pragma unroll
            for (int hf = 0; hf < 2; hf++) {
                int m = m0 + wm * 64 + mf * 16 + (l >> 2) + hf * 8;
                *(float2*)&out[(size_t)m * CC + col] =
                    make_float2(acc[mf][nf][hf*2 + 0], acc[mf][nf][hf*2 + 1]);
            }
        }
}

// ---------------------------------------------------------------------------
// Flash attention (fp16 mma, FA2 register layout). grid (16, 64), 256 thr.
// BR=128 (warp: 16 rows), BC=64, D=64. KV double-buffered via cp.async.
// QK^T 3-term (Qh*Kh + Ql*Kh + Qh*Kl); PV 2-term (P*Vh + P*Vl).
// Writes y as bf16 hi/lo [B,T,C].
// ---------------------------------------------------------------------------
#define FSTR 72
#define FKV_T (64*FSTR)              // 4608 elems per KV tile
#define FKV_STAGE_B (4*FKV_T*2)      // 36864 bytes per stage
#define FQ_T (128*FSTR)              // 9216 elems per Q tile
#define FQ_OFF (2*FKV_STAGE_B)       // 73728
#define FSMEM (FQ_OFF + 2*FQ_T*2)    // 110592

__device__ __forceinline__ void kv_issue(uint32_t sb, int stage, size_t hb, int jt) {
    const int t = threadIdx.x;
    const uint32_t stb = sb + stage * FKV_STAGE_B;
    #pragma unroll
    for (int i = 0; i < 8; i++) {
        const int tile = i >> 1;
        int rem = ((i & 1) << 8) | t;
        int row = rem >> 3;
        int c16 = rem & 7;
        const __half* src;
        size_t go = hb + (size_t)(jt * 64 + row) * DD + c16 * 8;
        if      (tile == 0) src = g_kh + go;
        else if (tile == 1) src = g_kl + go;
        else if (tile == 2) src = g_vh + go;
        else                src = g_vl + go;
        cp16(stb + (uint32_t)(tile * FKV_T + row * FSTR + c16 * 8) * 2, src);
    }
}

__global__ __launch_bounds__(256, 2)
void flash_mma() {
    extern __shared__ __align__(16) char fsm[];
    const uint32_t sb = smem_u32(fsm);

    const int tid = threadIdx.x;
    const int l   = tid & 31;
    const int w   = tid >> 5;            // 0..7
    const int qt  = (int)(gridDim.x - 1 - blockIdx.x);
    const int bh  = blockIdx.y;
    const int b   = bh >> 4;
    const int hh  = bh & 15;
    const size_t hb = (size_t)bh * TT * DD;

    // Q load (hi/lo) via cp.async
    #pragma unroll
    for (int i = 0; i < 8; i++) {
        const int tile = i >> 2;
        int rem = ((i & 3) << 8) | tid;
        int row = rem >> 3;
        int c16 = rem & 7;
        const __half* src = (tile == 0 ? g_qh : g_ql) + hb + (size_t)(qt * 128 + row) * DD + c16 * 8;
        cp16(sb + FQ_OFF + (uint32_t)(tile * FQ_T + row * FSTR + c16 * 8) * 2, src);
    }
    cp_commit();
    kv_issue(sb, 0, hb, 0);
    cp_commit();

    float s[8][4], o[8][4];
    float m0_ = -1e30f, m1_ = -1e30f, l0_ = 0.f, l1_ = 0.f;
    #pragma unroll
    for (int nf = 0; nf < 8; nf++)
        #pragma unroll
        for (int q = 0; q < 4; q++) o[nf][q] = 0.f;

    const uint32_t sQh = sb + FQ_OFF;
    const uint32_t sQl = sQh + FQ_T * 2;
    const uint32_t lrow = (l & 15);
    const uint32_t lkad = ((l >> 4) << 3);
    const int ntile = 2 * qt + 2;

    #pragma unroll 1
    for (int jt = 0; jt < ntile; jt++) {
        if (jt + 1 < ntile) {
            kv_issue(sb, (jt + 1) & 1, hb, jt + 1);
            cp_commit();
            cp_wait<1>();
        } else {
            cp_wait<0>();
        }
        __syncthreads();

        const uint32_t kvb = sb + (jt & 1) * FKV_STAGE_B;
        const uint32_t sKh = kvb;
        const uint32_t sKl = kvb + FKV_T * 2;
        const uint32_t sVh = kvb + 2 * FKV_T * 2;
        const uint32_t sVl = kvb + 3 * FKV_T * 2;

        // ---- S = Q K^T ----
        #pragma unroll
        for (int nf = 0; nf < 8; nf++)
            #pragma unroll
            for (int q = 0; q < 4; q++) s[nf][q] = 0.f;

        #pragma unroll
        for (int kd = 0; kd < 4; kd++) {
            uint32_t qh[4], ql[4];
            uint32_t offq = (uint32_t)((w * 16 + lrow) * FSTR + kd * 16 + lkad) * 2;
            ldsm4(qh, sQh + offq);
            ldsm4(ql, sQl + offq);
            #pragma unroll
            for (int p = 0; p < 4; p++) {
                uint32_t offk = (uint32_t)((p * 16 + lrow) * FSTR + kd * 16 + lkad) * 2;
                uint32_t rk[4], rkl[4];
                ldsm4(rk,  sKh + offk);
                ldsm4(rkl, sKl + offk);
                mma_f16(s[2*p],   qh, rk[0],  rk[2]);
                mma_f16(s[2*p+1], qh, rk[1],  rk[3]);
                mma_f16(s[2*p],   ql, rk[0],  rk[2]);
                mma_f16(s[2*p+1], ql, rk[1],  rk[3]);
                mma_f16(s[2*p],   qh, rkl[0], rkl[2]);
                mma_f16(s[2*p+1], qh, rkl[1], rkl[3]);
            }
        }

        // ---- scale + causal mask ----
        const int row_lo = qt * 128 + w * 16 + (l >> 2);
        const int row_hi = row_lo + 8;
        const int col0 = jt * 64 + (l & 3) * 2;
        #pragma unroll
        for (int nf = 0; nf < 8; nf++)
            #pragma unroll
            for (int q = 0; q < 4; q++) s[nf][q] *= 0.125f;
        if (jt >= 2 * qt) {
            #pragma unroll
            for (int nf = 0; nf < 8; nf++) {
                int c = col0 + nf * 8;
                if (c     > row_lo) s[nf][0] = -1e30f;
                if (c + 1 > row_lo) s[nf][1] = -1e30f;
                if (c     > row_hi) s[nf][2] = -1e30f;
                if (c + 1 > row_hi) s[nf][3] = -1e30f;
            }
        }

        // ---- online softmax (two row-halves per thread) ----
        float mt0 = -1e30f, mt1 = -1e30f;
        #pragma unroll
        for (int nf = 0; nf < 8; nf++) {
            mt0 = fmaxf(mt0, fmaxf(s[nf][0], s[nf][1]));
            mt1 = fmaxf(mt1, fmaxf(s[nf][2], s[nf][3]));
        }
        mt0 = fmaxf(mt0, __shfl_xor_sync(0xffffffffu, mt0, 1));
        mt0 = fmaxf(mt0, __shfl_xor_sync(0xffffffffu, mt0, 2));
        mt1 = fmaxf(mt1, __shfl_xor_sync(0xffffffffu, mt1, 1));
        mt1 = fmaxf(mt1, __shfl_xor_sync(0xffffffffu, mt1, 2));
        float mn0 = fmaxf(m0_, mt0);
        float mn1 = fmaxf(m1_, mt1);
        float cr0 = __expf(m0_ - mn0);
        float cr1 = __expf(m1_ - mn1);
        float rs0 = 0.f, rs1 = 0.f;
        #pragma unroll
        for (int nf = 0; nf < 8; nf++) {
            s[nf][0] = __expf(s[nf][0] - mn0);
            s[nf][1] = __expf(s[nf][1] - mn0);
            s[nf][2] = __expf(s[nf][2] - mn1);
            s[nf][3] = __expf(s[nf][3] - mn1);
            rs0 += s[nf][0] + s[nf][1];
            rs1 += s[nf][2] + s[nf][3];
        }
        rs0 += __shfl_xor_sync(0xffffffffu, rs0, 1);
        rs0 += __shfl_xor_sync(0xffffffffu, rs0, 2);
        rs1 += __shfl_xor_sync(0xffffffffu, rs1, 1);
        rs1 += __shfl_xor_sync(0xffffffffu, rs1, 2);
        l0_ = l0_ * cr0 + rs0;
        l1_ = l1_ * cr1 + rs1;
        m0_ = mn0; m1_ = mn1;
        #pragma unroll
        for (int nf = 0; nf < 8; nf++) {
            o[nf][0] *= cr0; o[nf][1] *= cr0;
            o[nf][2] *= cr1; o[nf][3] *= cr1;
        }

        // ---- P fragments (fp16) ----
        uint32_t ph[4][4];
        #pragma unroll
        for (int kk = 0; kk < 4; kk++) {
            ph[kk][0] = packh2(__float2half_rn(s[2*kk][0]),   __float2half_rn(s[2*kk][1]));
            ph[kk][1] = packh2(__float2half_rn(s[2*kk][2]),   __float2half_rn(s[2*kk][3]));
            ph[kk][2] = packh2(__float2half_rn(s[2*kk+1][0]), __float2half_rn(s[2*kk+1][1]));
            ph[kk][3] = packh2(__float2half_rn(s[2*kk+1][2]), __float2half_rn(s[2*kk+1][3]));
        }

        // ---- O += P V ----
        #pragma unroll
        for (int kk = 0; kk < 4; kk++) {
            #pragma unroll
            for (int p = 0; p < 4; p++) {
                uint32_t offv = (uint32_t)((kk * 16 + lrow) * FSTR + p * 16 + lkad) * 2;
                uint32_t rv[4], rl2[4];
                ldsm4t(rv,  sVh + offv);
                ldsm4t(rl2, sVl + offv);
                mma_f16(o[2*p],   ph[kk], rv[0],  rv[1]);
                mma_f16(o[2*p+1], ph[kk], rv[2],  rv[3]);
                mma_f16(o[2*p],   ph[kk], rl2[0], rl2[1]);
                mma_f16(o[2*p+1], ph[kk], rl2[2], rl2[3]);
            }
        }
        __syncthreads();
    }

    // ---- epilogue: normalize, split to bf16 hi/lo, write [B,T,C] ----
    const float inv0 = 1.f / l0_;
    const float inv1 = 1.f / l1_;
    const int t0 = qt * 128 + w * 16 + (l >> 2);
    #pragma unroll
    for (int nf = 0; nf < 8; nf++) {
        int col = hh * 64 + nf * 8 + (l & 3) * 2;
        #pragma unroll
        for (int hf = 0; hf < 2; hf++) {
            int t = t0 + hf * 8;
            float f0 = o[nf][hf*2 + 0] * (hf ? inv1 : inv0);
            float f1 = o[nf][hf*2 + 1] * (hf ? inv1 : inv0);
            __nv_bfloat16 b0 = __float2bfloat16(f0);
            __nv_bfloat16 b1 = __float2bfloat16(f1);
            __nv_bfloat16 e0 = __float2bfloat16(f0 - __bfloat162float(b0));
            __nv_bfloat16 e1 = __float2bfloat16(f1 - __bfloat162float(b1));
            size_t idx = ((size_t)(b * TT + t) << 10) + col;
            __nv_bfloat162 vh; vh.x = b0; vh.y = b1;
            __nv_bfloat162 vl; vl.x = e0; vl.y = e1;
            *(__nv_bfloat162*)&g_yhi[idx] = vh;
            *(__nv_bfloat162*)&g_ylo[idx] = vl;
        }
    }
}

// ---------------------------------------------------------------------------
extern "C" void kernel_launch(void* const* d_in, const int* in_sizes, int n_in,
                              void* d_out, int out_size)
{
    const float* x  = (const float*)d_in[0];
    const float* Wq = (const float*)d_in[1];
    const float* Wk = (const float*)d_in[2];
    const float* Wv = (const float*)d_in[3];
    const float* Wp = (const float*)d_in[4];
    float* out = (float*)d_out;

    cudaFuncSetAttribute(gemm_qkv,  cudaFuncAttributeMaxDynamicSharedMemorySize, GSMEM);
    cudaFuncSetAttribute(gemm_proj, cudaFuncAttributeMaxDynamicSharedMemorySize, GSMEM);
    cudaFuncSetAttribute(flash_mma, cudaFuncAttributeMaxDynamicSharedMemorySize, FSMEM);

    cvt_x<<<(MM*CC + 255)/256, 256>>>(x);
    cvt_w<<<(CC*CC + 255)/256, 256>>>(Wq, 0);
    cvt_w<<<(CC*CC + 255)/256, 256>>>(Wk, 1);
    cvt_w<<<(CC*CC + 255)/256, 256>>>(Wv, 2);
    cvt_w<<<(CC*CC + 255)/256, 256>>>(Wp, 3);

    gemm_qkv<<<dim3(CC/128, MM/128, 3), 256, GSMEM>>>();
    flash_mma<<<dim3(TT/128, BB*HH), 256, FSMEM>>>();
    gemm_proj<<<dim3(CC/128, MM/128), 256, GSMEM>>>(out);
}

// round 5
// speedup vs baseline: 5.2026x; 1.4862x over previous
#include <cuda_runtime.h>
#include <cuda_fp16.h>
#include <cstdint>

#define BB 4
#define TT 2048
#define CC 1024
#define HH 16
#define DD 64
#define MM (BB*TT)   // 8192

// ---------------------------------------------------------------------------
// Scratch (device globals, 16B aligned)
// ---------------------------------------------------------------------------
__device__ __align__(16) __half g_xh[(size_t)MM*CC];
__device__ __align__(16) __half g_xl[(size_t)MM*CC];
__device__ __align__(16) __half g_wh[(size_t)4*CC*CC];   // q,k,v,p (hi only)
__device__ __align__(16) __half g_qh[(size_t)MM*CC];     // [B,H,T,D]
__device__ __align__(16) __half g_ql[(size_t)MM*CC];
__device__ __align__(16) __half g_kh[(size_t)MM*CC];
__device__ __align__(16) __half g_vh[(size_t)MM*CC];
__device__ __align__(16) __half g_yh[(size_t)MM*CC];     // [B,T,C]
__device__ __align__(16) __half g_yl[(size_t)MM*CC];

// ---------------------------------------------------------------------------
// PTX helpers
// ---------------------------------------------------------------------------
__device__ __forceinline__ uint32_t smem_u32(const void* p) {
    uint32_t a;
    asm("{ .reg .u64 t; cvta.to.shared.u64 t, %1; cvt.u32.u64 %0, t; }"
        : "=r"(a) : "l"(p));
    return a;
}
__device__ __forceinline__ void cp16(uint32_t dst, const void* src) {
    asm volatile("cp.async.cg.shared.global [%0], [%1], 16;" :: "r"(dst), "l"(src));
}
__device__ __forceinline__ void cp_commit() {
    asm volatile("cp.async.commit_group;" ::: "memory");
}
template<int N> __device__ __forceinline__ void cp_wait() {
    asm volatile("cp.async.wait_group %0;" :: "n"(N) : "memory");
}
__device__ __forceinline__ void ldsm4(uint32_t* r, uint32_t a) {
    asm volatile("ldmatrix.sync.aligned.m8n8.x4.shared.b16 {%0,%1,%2,%3}, [%4];"
        : "=r"(r[0]), "=r"(r[1]), "=r"(r[2]), "=r"(r[3]) : "r"(a));
}
__device__ __forceinline__ void ldsm4t(uint32_t* r, uint32_t a) {
    asm volatile("ldmatrix.sync.aligned.m8n8.x4.trans.shared.b16 {%0,%1,%2,%3}, [%4];"
        : "=r"(r[0]), "=r"(r[1]), "=r"(r[2]), "=r"(r[3]) : "r"(a));
}
__device__ __forceinline__ void mma_f16(float* d, const uint32_t* a, uint32_t b0, uint32_t b1) {
    asm volatile(
        "mma.sync.aligned.m16n8k16.row.col.f32.f16.f16.f32 "
        "{%0,%1,%2,%3}, {%4,%5,%6,%7}, {%8,%9}, {%0,%1,%2,%3};"
        : "+f"(d[0]), "+f"(d[1]), "+f"(d[2]), "+f"(d[3])
        : "r"(a[0]), "r"(a[1]), "r"(a[2]), "r"(a[3]), "r"(b0), "r"(b1));
}
__device__ __forceinline__ uint32_t packh2(__half a, __half b) {
    __half2 h = __halves2half2(a, b);
    return *(uint32_t*)&h;
}

// ---------------------------------------------------------------------------
// Fused conversion: x -> fp16 hi/lo, W{q,k,v,p} -> fp16 hi. 2 elems/thread.
// ---------------------------------------------------------------------------
#define XPAIRS ((size_t)MM*CC/2)     // 4194304
#define WPAIRS ((size_t)CC*CC/2)     // 524288

__global__ void cvt_inputs(const float* __restrict__ x,
                           const float* __restrict__ Wq, const float* __restrict__ Wk,
                           const float* __restrict__ Wv, const float* __restrict__ Wp) {
    size_t i = (size_t)blockIdx.x * blockDim.x + threadIdx.x;
    if (i < XPAIRS) {
        float2 v = ((const float2*)x)[i];
        __half h0 = __float2half_rn(v.x), h1 = __float2half_rn(v.y);
        ((__half2*)g_xh)[i] = __halves2half2(h0, h1);
        ((__half2*)g_xl)[i] = __halves2half2(
            __float2half_rn(v.x - __half2float(h0)),
            __float2half_rn(v.y - __half2float(h1)));
    } else {
        size_t j = i - XPAIRS;
        int which = (int)(j >> 19);
        size_t wi = j & (WPAIRS - 1);
        const float* src = (which == 0) ? Wq : (which == 1) ? Wk : (which == 2) ? Wv : Wp;
        float2 v = ((const float2*)src)[wi];
        ((__half2*)g_wh)[(size_t)which * WPAIRS + wi] =
            __halves2half2(__float2half_rn(v.x), __float2half_rn(v.y));
    }
}

// ---------------------------------------------------------------------------
// GEMM: C[128x128] = (Ah+Al) * Wh^T, fp16 2-term, cp.async 2-stage pipeline.
// 256 threads, 8 warps (2m x 4n), warp tile 64x32.
// smem: 2 stages x 3 tiles (Ah,Al,Bh) of 128x32 fp16, row stride 40.
// ---------------------------------------------------------------------------
#define GSTR 40
#define GT_ELEMS (128*GSTR)          // 5120 elems per tile
#define GSTAGE_B (3*GT_ELEMS*2)      // 30720 bytes per stage
#define GSMEM (2*GSTAGE_B)           // 61440

__device__ __forceinline__ void gemm_issue(
    uint32_t sb, int stage,
    const __half* __restrict__ Ah, const __half* __restrict__ Al,
    const __half* __restrict__ Bh, int m0, int n0, int k0)
{
    const int t = threadIdx.x;
    const uint32_t stb = sb + stage * GSTAGE_B;
    #pragma unroll
    for (int i = 0; i < 6; i++) {
        const int tile = i >> 1;
        int rem = ((i & 1) << 8) | t;
        int row = rem >> 2;
        int c16 = rem & 3;
        const __half* src;
        if      (tile == 0) src = Ah + (size_t)(m0 + row) * CC + k0 + c16 * 8;
        else if (tile == 1) src = Al + (size_t)(m0 + row) * CC + k0 + c16 * 8;
        else                src = Bh + (size_t)(n0 + row) * CC + k0 + c16 * 8;
        cp16(stb + (uint32_t)(tile * GT_ELEMS + row * GSTR + c16 * 8) * 2, src);
    }
}

__device__ __forceinline__ void gemm_body(
    const __half* __restrict__ Ah, const __half* __restrict__ Al,
    const __half* __restrict__ Bh,
    int m0, int n0, uint32_t sb, float acc[4][4][4])
{
    const int l  = threadIdx.x & 31;
    const int wid = threadIdx.x >> 5;
    const int wm = wid >> 2;
    const int wn = wid & 3;

    #pragma unroll
    for (int mf = 0; mf < 4; mf++)
        #pragma unroll
        for (int nf = 0; nf < 4; nf++)
            #pragma unroll
            for (int q = 0; q < 4; q++) acc[mf][nf][q] = 0.f;

    gemm_issue(sb, 0, Ah, Al, Bh, m0, n0, 0);
    cp_commit();

    #pragma unroll 1
    for (int c = 0; c < 32; c++) {
        if (c + 1 < 32) {
            gemm_issue(sb, (c + 1) & 1, Ah, Al, Bh, m0, n0, (c + 1) * 32);
            cp_commit();
            cp_wait<1>();
        } else {
            cp_wait<0>();
        }
        __syncthreads();

        const uint32_t stb = sb + (c & 1) * GSTAGE_B;
        const uint32_t tAh = stb;
        const uint32_t tAl = stb + GT_ELEMS * 2;
        const uint32_t tBh = stb + 2 * GT_ELEMS * 2;
        const uint32_t lrow = (l & 15);
        const uint32_t lkad = ((l >> 4) << 3);

        #pragma unroll
        for (int ks = 0; ks < 32; ks += 16) {
            uint32_t ah[4][4], al[4][4];
            #pragma unroll
            for (int mf = 0; mf < 4; mf++) {
                uint32_t off = (uint32_t)((wm * 64 + mf * 16 + lrow) * GSTR + ks + lkad) * 2;
                ldsm4(ah[mf], tAh + off);
                ldsm4(al[mf], tAl + off);
            }
            uint32_t bh[4][2];
            #pragma unroll
            for (int p = 0; p < 2; p++) {
                uint32_t off = (uint32_t)((wn * 32 + p * 16 + lrow) * GSTR + ks + lkad) * 2;
                uint32_t r[4];
                ldsm4(r, tBh + off);
                bh[2*p][0]   = r[0]; bh[2*p][1]   = r[2];
                bh[2*p+1][0] = r[1]; bh[2*p+1][1] = r[3];
            }
            #pragma unroll
            for (int mf = 0; mf < 4; mf++)
                #pragma unroll
                for (int nf = 0; nf < 4; nf++) {
                    mma_f16(acc[mf][nf], ah[mf], bh[nf][0], bh[nf][1]);
                    mma_f16(acc[mf][nf], al[mf], bh[nf][0], bh[nf][1]);
                }
        }
        __syncthreads();
    }
}

// QKV projection: grid (8, 64, 3). q -> hi/lo fp16, k/v -> single fp16. [B,H,T,D]
__global__ __launch_bounds__(256, 2)
void gemm_qkv() {
    extern __shared__ __align__(16) char gsm[];
    const uint32_t sb = smem_u32(gsm);
    const int which = blockIdx.z;
    const int m0 = blockIdx.y * 128;
    const int n0 = blockIdx.x * 128;
    const __half* Wh = g_wh + (size_t)which * CC * CC;

    float acc[4][4][4];
    gemm_body(g_xh, g_xl, Wh, m0, n0, sb, acc);

    const int l  = threadIdx.x & 31;
    const int wid = threadIdx.x >> 5;
    const int wm = wid >> 2, wn = wid & 3;

    #pragma unroll
    for (int mf = 0; mf < 4; mf++) {
        #pragma unroll
        for (int nf = 0; nf < 4; nf++) {
            int col = n0 + wn * 32 + nf * 8 + (l & 3) * 2;
            int hh = col >> 6, d = col & 63;
            #pragma unroll
            for (int hf = 0; hf < 2; hf++) {
                int m = m0 + wm * 64 + mf * 16 + (l >> 2) + hf * 8;
                int b = m >> 11, t = m & (TT - 1);
                size_t idx = (((size_t)(b * HH + hh) * TT + t) << 6) + d;
                float f0 = acc[mf][nf][hf*2 + 0];
                float f1 = acc[mf][nf][hf*2 + 1];
                __half h0 = __float2half_rn(f0), h1 = __float2half_rn(f1);
                if (which == 0) {
                    *(__half2*)&g_qh[idx] = __halves2half2(h0, h1);
                    *(__half2*)&g_ql[idx] = __halves2half2(
                        __float2half_rn(f0 - __half2float(h0)),
                        __float2half_rn(f1 - __half2float(h1)));
                } else if (which == 1) {
                    *(__half2*)&g_kh[idx] = __halves2half2(h0, h1);
                } else {
                    *(__half2*)&g_vh[idx] = __halves2half2(h0, h1);
                }
            }
        }
    }
}

// Output projection: grid (8, 64); fp32 out
__global__ __launch_bounds__(256, 2)
void gemm_proj(float* __restrict__ out) {
    extern __shared__ __align__(16) char gsm[];
    const uint32_t sb = smem_u32(gsm);
    const int m0 = blockIdx.y * 128;
    const int n0 = blockIdx.x * 128;
    const __half* Wh = g_wh + (size_t)3 * CC * CC;

    float acc[4][4][4];
    gemm_body(g_yh, g_yl, Wh, m0, n0, sb, acc);

    const int l  = threadIdx.x & 31;
    const int wid = threadIdx.x >> 5;
    const int wm = wid >> 2, wn = wid & 3;

    #pragma unroll
    for (int mf = 0; mf < 4; mf++)
        #pragma unroll
        for (int nf = 0; nf < 4; nf++) {
            int col = n0 + wn * 32 + nf * 8 + (l & 3) * 2;
            #pragma unroll
            for (int hf = 0; hf < 2; hf++) {
                int m = m0 + wm * 64 + mf * 16 + (l >> 2) + hf * 8;
                *(float2*)&out[(size_t)m * CC + col] =
                    make_float2(acc[mf][nf][hf*2 + 0], acc[mf][nf][hf*2 + 1]);
            }
        }
}

// ---------------------------------------------------------------------------
// Flash attention. grid (16, 64), 256 thr. BR=128 (16/warp), BC=64, D=64.
// QK^T: (Qh+Ql)*Kh (2-term). PV: P*Vh (1-term). KV double-buffered cp.async.
// ---------------------------------------------------------------------------
#define FSTR 72
#define FKV_T (64*FSTR)              // 4608 elems per KV tile
#define FKV_STAGE_B (2*FKV_T*2)      // 18432 bytes per stage (Kh, Vh)
#define FQ_T (128*FSTR)              // 9216 elems per Q tile
#define FQ_OFF (2*FKV_STAGE_B)       // 36864
#define FSMEM (FQ_OFF + 2*FQ_T*2)    // 73728

__device__ __forceinline__ void kv_issue(uint32_t sb, int stage, size_t hb, int jt) {
    const int t = threadIdx.x;
    const uint32_t stb = sb + stage * FKV_STAGE_B;
    #pragma unroll
    for (int i = 0; i < 4; i++) {
        const int tile = i >> 1;
        int rem = ((i & 1) << 8) | t;
        int row = rem >> 3;
        int c16 = rem & 7;
        size_t go = hb + (size_t)(jt * 64 + row) * DD + c16 * 8;
        const __half* src = (tile == 0) ? (g_kh + go) : (g_vh + go);
        cp16(stb + (uint32_t)(tile * FKV_T + row * FSTR + c16 * 8) * 2, src);
    }
}

__global__ __launch_bounds__(256, 2)
void flash_mma() {
    extern __shared__ __align__(16) char fsm[];
    const uint32_t sb = smem_u32(fsm);

    const int tid = threadIdx.x;
    const int l   = tid & 31;
    const int w   = tid >> 5;
    const int qt  = (int)(gridDim.x - 1 - blockIdx.x);
    const int bh  = blockIdx.y;
    const int b   = bh >> 4;
    const int hh  = bh & 15;
    const size_t hb = (size_t)bh * TT * DD;

    // Q load (hi/lo) via cp.async
    #pragma unroll
    for (int i = 0; i < 8; i++) {
        const int tile = i >> 2;
        int rem = ((i & 3) << 8) | tid;
        int row = rem >> 3;
        int c16 = rem & 7;
        const __half* src = (tile == 0 ? g_qh : g_ql) + hb + (size_t)(qt * 128 + row) * DD + c16 * 8;
        cp16(sb + FQ_OFF + (uint32_t)(tile * FQ_T + row * FSTR + c16 * 8) * 2, src);
    }
    cp_commit();
    kv_issue(sb, 0, hb, 0);
    cp_commit();

    float s[8][4], o[8][4];
    float m0_ = -1e30f, m1_ = -1e30f, l0_ = 0.f, l1_ = 0.f;
    #pragma unroll
    for (int nf = 0; nf < 8; nf++)
        #pragma unroll
        for (int q = 0; q < 4; q++) o[nf][q] = 0.f;

    const uint32_t sQh = sb + FQ_OFF;
    const uint32_t sQl = sQh + FQ_T * 2;
    const uint32_t lrow = (l & 15);
    const uint32_t lkad = ((l >> 4) << 3);
    const int ntile = 2 * qt + 2;

    #pragma unroll 1
    for (int jt = 0; jt < ntile; jt++) {
        if (jt + 1 < ntile) {
            kv_issue(sb, (jt + 1) & 1, hb, jt + 1);
            cp_commit();
            cp_wait<1>();
        } else {
            cp_wait<0>();
        }
        __syncthreads();

        const uint32_t kvb = sb + (jt & 1) * FKV_STAGE_B;
        const uint32_t sKh = kvb;
        const uint32_t sVh = kvb + FKV_T * 2;

        // ---- S = Q K^T (2-term) ----
        #pragma unroll
        for (int nf = 0; nf < 8; nf++)
            #pragma unroll
            for (int q = 0; q < 4; q++) s[nf][q] = 0.f;

        #pragma unroll
        for (int kd = 0; kd < 4; kd++) {
            uint32_t qh[4], ql[4];
            uint32_t offq = (uint32_t)((w * 16 + lrow) * FSTR + kd * 16 + lkad) * 2;
            ldsm4(qh, sQh + offq);
            ldsm4(ql, sQl + offq);
            #pragma unroll
            for (int p = 0; p < 4; p++) {
                uint32_t offk = (uint32_t)((p * 16 + lrow) * FSTR + kd * 16 + lkad) * 2;
                uint32_t rk[4];
                ldsm4(rk, sKh + offk);
                mma_f16(s[2*p],   qh, rk[0], rk[2]);
                mma_f16(s[2*p+1], qh, rk[1], rk[3]);
                mma_f16(s[2*p],   ql, rk[0], rk[2]);
                mma_f16(s[2*p+1], ql, rk[1], rk[3]);
            }
        }

        // ---- scale + causal mask ----
        const int row_lo = qt * 128 + w * 16 + (l >> 2);
        const int row_hi = row_lo + 8;
        const int col0 = jt * 64 + (l & 3) * 2;
        #pragma unroll
        for (int nf = 0; nf < 8; nf++)
            #pragma unroll
            for (int q = 0; q < 4; q++) s[nf][q] *= 0.125f;
        if (jt >= 2 * qt) {
            #pragma unroll
            for (int nf = 0; nf < 8; nf++) {
                int c = col0 + nf * 8;
                if (c     > row_lo) s[nf][0] = -1e30f;
                if (c + 1 > row_lo) s[nf][1] = -1e30f;
                if (c     > row_hi) s[nf][2] = -1e30f;
                if (c + 1 > row_hi) s[nf][3] = -1e30f;
            }
        }

        // ---- online softmax ----
        float mt0 = -1e30f, mt1 = -1e30f;
        #pragma unroll
        for (int nf = 0; nf < 8; nf++) {
            mt0 = fmaxf(mt0, fmaxf(s[nf][0], s[nf][1]));
            mt1 = fmaxf(mt1, fmaxf(s[nf][2], s[nf][3]));
        }
        mt0 = fmaxf(mt0, __shfl_xor_sync(0xffffffffu, mt0, 1));
        mt0 = fmaxf(mt0, __shfl_xor_sync(0xffffffffu, mt0, 2));
        mt1 = fmaxf(mt1, __shfl_xor_sync(0xffffffffu, mt1, 1));
        mt1 = fmaxf(mt1, __shfl_xor_sync(0xffffffffu, mt1, 2));
        float mn0 = fmaxf(m0_, mt0);
        float mn1 = fmaxf(m1_, mt1);
        float cr0 = __expf(m0_ - mn0);
        float cr1 = __expf(m1_ - mn1);
        float rs0 = 0.f, rs1 = 0.f;
        #pragma unroll
        for (int nf = 0; nf < 8; nf++) {
            s[nf][0] = __expf(s[nf][0] - mn0);
            s[nf][1] = __expf(s[nf][1] - mn0);
            s[nf][2] = __expf(s[nf][2] - mn1);
            s[nf][3] = __expf(s[nf][3] - mn1);
            rs0 += s[nf][0] + s[nf][1];
            rs1 += s[nf][2] + s[nf][3];
        }
        rs0 += __shfl_xor_sync(0xffffffffu, rs0, 1);
        rs0 += __shfl_xor_sync(0xffffffffu, rs0, 2);
        rs1 += __shfl_xor_sync(0xffffffffu, rs1, 1);
        rs1 += __shfl_xor_sync(0xffffffffu, rs1, 2);
        l0_ = l0_ * cr0 + rs0;
        l1_ = l1_ * cr1 + rs1;
        m0_ = mn0; m1_ = mn1;
        #pragma unroll
        for (int nf = 0; nf < 8; nf++) {
            o[nf][0] *= cr0; o[nf][1] *= cr0;
            o[nf][2] *= cr1; o[nf][3] *= cr1;
        }

        // ---- P fragments (fp16) ----
        uint32_t ph[4][4];
        #pragma unroll
        for (int kk = 0; kk < 4; kk++) {
            ph[kk][0] = packh2(__float2half_rn(s[2*kk][0]),   __float2half_rn(s[2*kk][1]));
            ph[kk][1] = packh2(__float2half_rn(s[2*kk][2]),   __float2half_rn(s[2*kk][3]));
            ph[kk][2] = packh2(__float2half_rn(s[2*kk+1][0]), __float2half_rn(s[2*kk+1][1]));
            ph[kk][3] = packh2(__float2half_rn(s[2*kk+1][2]), __float2half_rn(s[2*kk+1][3]));
        }

        // ---- O += P V (1-term) ----
        #pragma unroll
        for (int kk = 0; kk < 4; kk++) {
            #pragma unroll
            for (int p = 0; p < 4; p++) {
                uint32_t offv = (uint32_t)((kk * 16 + lrow) * FSTR + p * 16 + lkad) * 2;
                uint32_t rv[4];
                ldsm4t(rv, sVh + offv);
                mma_f16(o[2*p],   ph[kk], rv[0], rv[1]);
                mma_f16(o[2*p+1], ph[kk], rv[2], rv[3]);
            }
        }
        __syncthreads();
    }

    // ---- epilogue: normalize, split fp16 hi/lo, write [B,T,C] ----
    const float inv0 = 1.f / l0_;
    const float inv1 = 1.f / l1_;
    const int t0 = qt * 128 + w * 16 + (l >> 2);
    #pragma unroll
    for (int nf = 0; nf < 8; nf++) {
        int col = hh * 64 + nf * 8 + (l & 3) * 2;
        #pragma unroll
        for (int hf = 0; hf < 2; hf++) {
            int t = t0 + hf * 8;
            float f0 = o[nf][hf*2 + 0] * (hf ? inv1 : inv0);
            float f1 = o[nf][hf*2 + 1] * (hf ? inv1 : inv0);
            __half h0 = __float2half_rn(f0), h1 = __float2half_rn(f1);
            size_t idx = ((size_t)(b * TT + t) << 10) + col;
            *(__half2*)&g_yh[idx] = __halves2half2(h0, h1);
            *(__half2*)&g_yl[idx] = __halves2half2(
                __float2half_rn(f0 - __half2float(h0)),
                __float2half_rn(f1 - __half2float(h1)));
        }
    }
}

// ---------------------------------------------------------------------------
extern "C" void kernel_launch(void* const* d_in, const int* in_sizes, int n_in,
                              void* d_out, int out_size)
{
    const float* x  = (const float*)d_in[0];
    const float* Wq = (const float*)d_in[1];
    const float* Wk = (const float*)d_in[2];
    const float* Wv = (const float*)d_in[3];
    const float* Wp = (const float*)d_in[4];
    float* out = (float*)d_out;

    cudaFuncSetAttribute(gemm_qkv,  cudaFuncAttributeMaxDynamicSharedMemorySize, GSMEM);
    cudaFuncSetAttribute(gemm_proj, cudaFuncAttributeMaxDynamicSharedMemorySize, GSMEM);
    cudaFuncSetAttribute(flash_mma, cudaFuncAttributeMaxDynamicSharedMemorySize, FSMEM);

    size_t total_pairs = XPAIRS + 4 * WPAIRS;   // 6M
    cvt_inputs<<<(unsigned)((total_pairs + 255) / 256), 256>>>(x, Wq, Wk, Wv, Wp);

    gemm_qkv<<<dim3(CC/128, MM/128, 3), 256, GSMEM>>>();
    flash_mma<<<dim3(TT/128, BB*HH), 256, FSMEM>>>();
    gemm_proj<<<dim3(CC/128, MM/128), 256, GSMEM>>>(out);
}

// round 8
// speedup vs baseline: 5.2686x; 1.0127x over previous
#include <cuda_runtime.h>
#include <cuda_fp16.h>
#include <cstdint>

#define BB 4
#define TT 2048
#define CC 1024
#define HH 16
#define DD 64
#define MM (BB*TT)   // 8192

// ---------------------------------------------------------------------------
// Scratch (device globals, 16B aligned)
// ---------------------------------------------------------------------------
__device__ __align__(16) __half g_xh[(size_t)MM*CC];
__device__ __align__(16) __half g_xl[(size_t)MM*CC];
__device__ __align__(16) __half g_wh[(size_t)4*CC*CC];   // q,k,v,p (hi only)
__device__ __align__(16) __half g_qh[(size_t)MM*CC];     // [B,H,T,D]
__device__ __align__(16) __half g_ql[(size_t)MM*CC];
__device__ __align__(16) __half g_kh[(size_t)MM*CC];
__device__ __align__(16) __half g_vh[(size_t)MM*CC];
__device__ __align__(16) __half g_yh[(size_t)MM*CC];     // [B,T,C]
__device__ __align__(16) __half g_yl[(size_t)MM*CC];

// ---------------------------------------------------------------------------
// PTX helpers
// ---------------------------------------------------------------------------
__device__ __forceinline__ uint32_t smem_u32(const void* p) {
    uint32_t a;
    asm("{ .reg .u64 t; cvta.to.shared.u64 t, %1; cvt.u32.u64 %0, t; }"
        : "=r"(a) : "l"(p));
    return a;
}
__device__ __forceinline__ void cp16(uint32_t dst, const void* src) {
    asm volatile("cp.async.cg.shared.global [%0], [%1], 16;" :: "r"(dst), "l"(src));
}
__device__ __forceinline__ void cp_commit() {
    asm volatile("cp.async.commit_group;" ::: "memory");
}
template<int N> __device__ __forceinline__ void cp_wait() {
    asm volatile("cp.async.wait_group %0;" :: "n"(N) : "memory");
}
__device__ __forceinline__ void ldsm4(uint32_t* r, uint32_t a) {
    asm volatile("ldmatrix.sync.aligned.m8n8.x4.shared.b16 {%0,%1,%2,%3}, [%4];"
        : "=r"(r[0]), "=r"(r[1]), "=r"(r[2]), "=r"(r[3]) : "r"(a));
}
__device__ __forceinline__ void ldsm4t(uint32_t* r, uint32_t a) {
    asm volatile("ldmatrix.sync.aligned.m8n8.x4.trans.shared.b16 {%0,%1,%2,%3}, [%4];"
        : "=r"(r[0]), "=r"(r[1]), "=r"(r[2]), "=r"(r[3]) : "r"(a));
}
__device__ __forceinline__ void mma_f16(float* d, const uint32_t* a, uint32_t b0, uint32_t b1) {
    asm volatile(
        "mma.sync.aligned.m16n8k16.row.col.f32.f16.f16.f32 "
        "{%0,%1,%2,%3}, {%4,%5,%6,%7}, {%8,%9}, {%0,%1,%2,%3};"
        : "+f"(d[0]), "+f"(d[1]), "+f"(d[2]), "+f"(d[3])
        : "r"(a[0]), "r"(a[1]), "r"(a[2]), "r"(a[3]), "r"(b0), "r"(b1));
}
__device__ __forceinline__ uint32_t packh2(__half a, __half b) {
    __half2 h = __halves2half2(a, b);
    return *(uint32_t*)&h;
}

// ---------------------------------------------------------------------------
// Fused conversion: x -> fp16 hi/lo, W{q,k,v,p} -> fp16 hi. 2 elems/thread.
// ---------------------------------------------------------------------------
#define XPAIRS ((size_t)MM*CC/2)     // 4194304
#define WPAIRS ((size_t)CC*CC/2)     // 524288

__global__ void cvt_inputs(const float* __restrict__ x,
                           const float* __restrict__ Wq, const float* __restrict__ Wk,
                           const float* __restrict__ Wv, const float* __restrict__ Wp) {
    size_t i = (size_t)blockIdx.x * blockDim.x + threadIdx.x;
    if (i < XPAIRS) {
        float2 v = ((const float2*)x)[i];
        __half h0 = __float2half_rn(v.x), h1 = __float2half_rn(v.y);
        ((__half2*)g_xh)[i] = __halves2half2(h0, h1);
        ((__half2*)g_xl)[i] = __halves2half2(
            __float2half_rn(v.x - __half2float(h0)),
            __float2half_rn(v.y - __half2float(h1)));
    } else {
        size_t j = i - XPAIRS;
        int which = (int)(j >> 19);
        size_t wi = j & (WPAIRS - 1);
        const float* src = (which == 0) ? Wq : (which == 1) ? Wk : (which == 2) ? Wv : Wp;
        float2 v = ((const float2*)src)[wi];
        ((__half2*)g_wh)[(size_t)which * WPAIRS + wi] =
            __halves2half2(__float2half_rn(v.x), __float2half_rn(v.y));
    }
}

// ---------------------------------------------------------------------------
// GEMM: C[128x128] = (Ah+Al) * Wh^T, fp16 2-term, cp.async 3-stage pipeline,
// one __syncthreads per 32-K chunk. 256 threads, 8 warps (2m x 4n), wt 64x32.
// smem: 3 stages x 3 tiles (Ah,Al,Bh) of 128x32 fp16, row stride 40.
// ---------------------------------------------------------------------------
#define GSTR 40
#define GT_ELEMS (128*GSTR)          // 5120 elems per tile
#define GSTAGE_B (3*GT_ELEMS*2)      // 30720 bytes per stage
#define GSMEM (3*GSTAGE_B)           // 92160

__device__ __forceinline__ void gemm_issue(
    uint32_t sb, int stage,
    const __half* __restrict__ Ah, const __half* __restrict__ Al,
    const __half* __restrict__ Bh, int m0, int n0, int k0)
{
    const int t = threadIdx.x;
    const uint32_t stb = sb + stage * GSTAGE_B;
    #pragma unroll
    for (int i = 0; i < 6; i++) {
        const int tile = i >> 1;
        int rem = ((i & 1) << 8) | t;
        int row = rem >> 2;
        int c16 = rem & 3;
        const __half* src;
        if      (tile == 0) src = Ah + (size_t)(m0 + row) * CC + k0 + c16 * 8;
        else if (tile == 1) src = Al + (size_t)(m0 + row) * CC + k0 + c16 * 8;
        else                src = Bh + (size_t)(n0 + row) * CC + k0 + c16 * 8;
        cp16(stb + (uint32_t)(tile * GT_ELEMS + row * GSTR + c16 * 8) * 2, src);
    }
}

__device__ __forceinline__ void gemm_body(
    const __half* __restrict__ Ah, const __half* __restrict__ Al,
    const __half* __restrict__ Bh,
    int m0, int n0, uint32_t sb, float acc[4][4][4])
{
    const int l  = threadIdx.x & 31;
    const int wid = threadIdx.x >> 5;
    const int wm = wid >> 2;
    const int wn = wid & 3;

    #pragma unroll
    for (int mf = 0; mf < 4; mf++)
        #pragma unroll
        for (int nf = 0; nf < 4; nf++)
            #pragma unroll
            for (int q = 0; q < 4; q++) acc[mf][nf][q] = 0.f;

    gemm_issue(sb, 0, Ah, Al, Bh, m0, n0, 0);
    cp_commit();
    gemm_issue(sb, 1, Ah, Al, Bh, m0, n0, 32);
    cp_commit();

    const uint32_t lrow = (l & 15);
    const uint32_t lkad = ((l >> 4) << 3);

    #pragma unroll 1
    for (int c = 0; c < 32; c++) {
        cp_wait<1>();            // chunk c landed
        __syncthreads();         // all warps done with chunk c-1 -> stage reusable
        if (c + 2 < 32)
            gemm_issue(sb, (c + 2) % 3, Ah, Al, Bh, m0, n0, (c + 2) * 32);
        cp_commit();             // uniform group count (may be empty)

        const uint32_t stb = sb + (c % 3) * GSTAGE_B;
        const uint32_t tAh = stb;
        const uint32_t tAl = stb + GT_ELEMS * 2;
        const uint32_t tBh = stb + 2 * GT_ELEMS * 2;

        #pragma unroll
        for (int ks = 0; ks < 32; ks += 16) {
            uint32_t ah[4][4], al[4][4];
            #pragma unroll
            for (int mf = 0; mf < 4; mf++) {
                uint32_t off = (uint32_t)((wm * 64 + mf * 16 + lrow) * GSTR + ks + lkad) * 2;
                ldsm4(ah[mf], tAh + off);
                ldsm4(al[mf], tAl + off);
            }
            uint32_t bh[4][2];
            #pragma unroll
            for (int p = 0; p < 2; p++) {
                uint32_t off = (uint32_t)((wn * 32 + p * 16 + lrow) * GSTR + ks + lkad) * 2;
                uint32_t r[4];
                ldsm4(r, tBh + off);
                bh[2*p][0]   = r[0]; bh[2*p][1]   = r[2];
                bh[2*p+1][0] = r[1]; bh[2*p+1][1] = r[3];
            }
            // hi sweep, then lo sweep: same-acc reuse distance = 16 MMAs
            #pragma unroll
            for (int mf = 0; mf < 4; mf++)
                #pragma unroll
                for (int nf = 0; nf < 4; nf++)
                    mma_f16(acc[mf][nf], ah[mf], bh[nf][0], bh[nf][1]);
            #pragma unroll
            for (int mf = 0; mf < 4; mf++)
                #pragma unroll
                for (int nf = 0; nf < 4; nf++)
                    mma_f16(acc[mf][nf], al[mf], bh[nf][0], bh[nf][1]);
        }
    }
}

// QKV projection: grid (8, 64, 3). q -> hi/lo fp16, k/v -> single fp16. [B,H,T,D]
__global__ __launch_bounds__(256, 2)
void gemm_qkv() {
    extern __shared__ __align__(16) char gsm[];
    const uint32_t sb = smem_u32(gsm);
    const int which = blockIdx.z;
    const int m0 = blockIdx.y * 128;
    const int n0 = blockIdx.x * 128;
    const __half* Wh = g_wh + (size_t)which * CC * CC;

    float acc[4][4][4];
    gemm_body(g_xh, g_xl, Wh, m0, n0, sb, acc);

    const int l  = threadIdx.x & 31;
    const int wid = threadIdx.x >> 5;
    const int wm = wid >> 2, wn = wid & 3;

    #pragma unroll
    for (int mf = 0; mf < 4; mf++) {
        #pragma unroll
        for (int nf = 0; nf < 4; nf++) {
            int col = n0 + wn * 32 + nf * 8 + (l & 3) * 2;
            int hh = col >> 6, d = col & 63;
            #pragma unroll
            for (int hf = 0; hf < 2; hf++) {
                int m = m0 + wm * 64 + mf * 16 + (l >> 2) + hf * 8;
                int b = m >> 11, t = m & (TT - 1);
                size_t idx = (((size_t)(b * HH + hh) * TT + t) << 6) + d;
                float f0 = acc[mf][nf][hf*2 + 0];
                float f1 = acc[mf][nf][hf*2 + 1];
                __half h0 = __float2half_rn(f0), h1 = __float2half_rn(f1);
                if (which == 0) {
                    *(__half2*)&g_qh[idx] = __halves2half2(h0, h1);
                    *(__half2*)&g_ql[idx] = __halves2half2(
                        __float2half_rn(f0 - __half2float(h0)),
                        __float2half_rn(f1 - __half2float(h1)));
                } else if (which == 1) {
                    *(__half2*)&g_kh[idx] = __halves2half2(h0, h1);
                } else {
                    *(__half2*)&g_vh[idx] = __halves2half2(h0, h1);
                }
            }
        }
    }
}

// Output projection: grid (8, 64); fp32 out
__global__ __launch_bounds__(256, 2)
void gemm_proj(float* __restrict__ out) {
    extern __shared__ __align__(16) char gsm[];
    const uint32_t sb = smem_u32(gsm);
    const int m0 = blockIdx.y * 128;
    const int n0 = blockIdx.x * 128;
    const __half* Wh = g_wh + (size_t)3 * CC * CC;

    float acc[4][4][4];
    gemm_body(g_yh, g_yl, Wh, m0, n0, sb, acc);

    const int l  = threadIdx.x & 31;
    const int wid = threadIdx.x >> 5;
    const int wm = wid >> 2, wn = wid & 3;

    #pragma unroll
    for (int mf = 0; mf < 4; mf++)
        #pragma unroll
        for (int nf = 0; nf < 4; nf++) {
            int col = n0 + wn * 32 + nf * 8 + (l & 3) * 2;
            #pragma unroll
            for (int hf = 0; hf < 2; hf++) {
                int m = m0 + wm * 64 + mf * 16 + (l >> 2) + hf * 8;
                *(float2*)&out[(size_t)m * CC + col] =
                    make_float2(acc[mf][nf][hf*2 + 0], acc[mf][nf][hf*2 + 1]);
            }
        }
}

// ---------------------------------------------------------------------------
// Flash attention. grid (16, 64), 256 thr. BR=128 (16/warp), BC=64, D=64.
// QK^T: (Qh+Ql)*Kh (2-term). PV: P*Vh (1-term).
// KV 3-stage cp.async ring, one __syncthreads per KV tile.
// ---------------------------------------------------------------------------
#define FSTR 72
#define FKV_T (64*FSTR)              // 4608 elems per KV tile
#define FKV_STAGE_B (2*FKV_T*2)      // 18432 bytes per stage (Kh, Vh)
#define FQ_T (128*FSTR)              // 9216 elems per Q tile
#define FQ_OFF (3*FKV_STAGE_B)       // 55296
#define FSMEM (FQ_OFF + 2*FQ_T*2)    // 92160

__device__ __forceinline__ void kv_issue(uint32_t sb, int stage, size_t hb, int jt) {
    const int t = threadIdx.x;
    const uint32_t stb = sb + stage * FKV_STAGE_B;
    #pragma unroll
    for (int i = 0; i < 4; i++) {
        const int tile = i >> 1;
        int rem = ((i & 1) << 8) | t;
        int row = rem >> 3;
        int c16 = rem & 7;
        size_t go = hb + (size_t)(jt * 64 + row) * DD + c16 * 8;
        const __half* src = (tile == 0) ? (g_kh + go) : (g_vh + go);
        cp16(stb + (uint32_t)(tile * FKV_T + row * FSTR + c16 * 8) * 2, src);
    }
}

__global__ __launch_bounds__(256, 2)
void flash_mma() {
    extern __shared__ __align__(16) char fsm[];
    const uint32_t sb = smem_u32(fsm);

    const int tid = threadIdx.x;
    const int l   = tid & 31;
    const int w   = tid >> 5;
    const int qt  = (int)(gridDim.x - 1 - blockIdx.x);
    const int bh  = blockIdx.y;
    const int b   = bh >> 4;
    const int hh  = bh & 15;
    const size_t hb = (size_t)bh * TT * DD;
    const int ntile = 2 * qt + 2;

    // Q load (hi/lo) + kv0 in group 0; kv1 in group 1
    #pragma unroll
    for (int i = 0; i < 8; i++) {
        const int tile = i >> 2;
        int rem = ((i & 3) << 8) | tid;
        int row = rem >> 3;
        int c16 = rem & 7;
        const __half* src = (tile == 0 ? g_qh : g_ql) + hb + (size_t)(qt * 128 + row) * DD + c16 * 8;
        cp16(sb + FQ_OFF + (uint32_t)(tile * FQ_T + row * FSTR + c16 * 8) * 2, src);
    }
    kv_issue(sb, 0, hb, 0);
    cp_commit();
    kv_issue(sb, 1, hb, 1);     // ntile >= 2 always
    cp_commit();

    float s[8][4], o[8][4];
    float m0_ = -1e30f, m1_ = -1e30f, l0_ = 0.f, l1_ = 0.f;
    #pragma unroll
    for (int nf = 0; nf < 8; nf++)
        #pragma unroll
        for (int q = 0; q < 4; q++) o[nf][q] = 0.f;

    const uint32_t sQh = sb + FQ_OFF;
    const uint32_t sQl = sQh + FQ_T * 2;
    const uint32_t lrow = (l & 15);
    const uint32_t lkad = ((l >> 4) << 3);

    #pragma unroll 1
    for (int jt = 0; jt < ntile; jt++) {
        cp_wait<1>();            // kv tile jt landed
        __syncthreads();         // all warps done with tile jt-1
        if (jt + 2 < ntile)
            kv_issue(sb, (jt + 2) % 3, hb, jt + 2);
        cp_commit();             // uniform group count

        const uint32_t kvb = sb + (jt % 3) * FKV_STAGE_B;
        const uint32_t sKh = kvb;
        const uint32_t sVh = kvb + FKV_T * 2;

        // ---- S = Q K^T (2-term, hi sweep then lo sweep) ----
        #pragma unroll
        for (int nf = 0; nf < 8; nf++)
            #pragma unroll
            for (int q = 0; q < 4; q++) s[nf][q] = 0.f;

        #pragma unroll
        for (int kd = 0; kd < 4; kd++) {
            uint32_t qh[4], ql[4];
            uint32_t offq = (uint32_t)((w * 16 + lrow) * FSTR + kd * 16 + lkad) * 2;
            ldsm4(qh, sQh + offq);
            ldsm4(ql, sQl + offq);
            uint32_t rk[4][4];
            #pragma unroll
            for (int p = 0; p < 4; p++) {
                uint32_t offk = (uint32_t)((p * 16 + lrow) * FSTR + kd * 16 + lkad) * 2;
                ldsm4(rk[p], sKh + offk);
            }
            #pragma unroll
            for (int p = 0; p < 4; p++) {
                mma_f16(s[2*p],   qh, rk[p][0], rk[p][2]);
                mma_f16(s[2*p+1], qh, rk[p][1], rk[p][3]);
            }
            #pragma unroll
            for (int p = 0; p < 4; p++) {
                mma_f16(s[2*p],   ql, rk[p][0], rk[p][2]);
                mma_f16(s[2*p+1], ql, rk[p][1], rk[p][3]);
            }
        }

        // ---- scale + causal mask ----
        const int row_lo = qt * 128 + w * 16 + (l >> 2);
        const int row_hi = row_lo + 8;
        const int col0 = jt * 64 + (l & 3) * 2;
        #pragma unroll
        for (int nf = 0; nf < 8; nf++)
            #pragma unroll
            for (int q = 0; q < 4; q++) s[nf][q] *= 0.125f;
        if (jt >= 2 * qt) {
            #pragma unroll
            for (int nf = 0; nf < 8; nf++) {
                int c = col0 + nf * 8;
                if (c     > row_lo) s[nf][0] = -1e30f;
                if (c + 1 > row_lo) s[nf][1] = -1e30f;
                if (c     > row_hi) s[nf][2] = -1e30f;
                if (c + 1 > row_hi) s[nf][3] = -1e30f;
            }
        }

        // ---- online softmax ----
        float mt0 = -1e30f, mt1 = -1e30f;
        #pragma unroll
        for (int nf = 0; nf < 8; nf++) {
            mt0 = fmaxf(mt0, fmaxf(s[nf][0], s[nf][1]));
            mt1 = fmaxf(mt1, fmaxf(s[nf][2], s[nf][3]));
        }
        mt0 = fmaxf(mt0, __shfl_xor_sync(0xffffffffu, mt0, 1));
        mt0 = fmaxf(mt0, __shfl_xor_sync(0xffffffffu, mt0, 2));
        mt1 = fmaxf(mt1, __shfl_xor_sync(0xffffffffu, mt1, 1));
        mt1 = fmaxf(mt1, __shfl_xor_sync(0xffffffffu, mt1, 2));
        float mn0 = fmaxf(m0_, mt0);
        float mn1 = fmaxf(m1_, mt1);
        float cr0 = __expf(m0_ - mn0);
        float cr1 = __expf(m1_ - mn1);
        float rs0 = 0.f, rs1 = 0.f;
        #pragma unroll
        for (int nf = 0; nf < 8; nf++) {
            s[nf][0] = __expf(s[nf][0] - mn0);
            s[nf][1] = __expf(s[nf][1] - mn0);
            s[nf][2] = __expf(s[nf][2] - mn1);
            s[nf][3] = __expf(s[nf][3] - mn1);
            rs0 += s[nf][0] + s[nf][1];
            rs1 += s[nf][2] + s[nf][3];
        }
        rs0 += __shfl_xor_sync(0xffffffffu, rs0, 1);
        rs0 += __shfl_xor_sync(0xffffffffu, rs0, 2);
        rs1 += __shfl_xor_sync(0xffffffffu, rs1, 1);
        rs1 += __shfl_xor_sync(0xffffffffu, rs1, 2);
        l0_ = l0_ * cr0 + rs0;
        l1_ = l1_ * cr1 + rs1;
        m0_ = mn0; m1_ = mn1;
        #pragma unroll
        for (int nf = 0; nf < 8; nf++) {
            o[nf][0] *= cr0; o[nf][1] *= cr0;
            o[nf][2] *= cr1; o[nf][3] *= cr1;
        }

        // ---- P fragments (fp16) ----
        uint32_t ph[4][4];
        #pragma unroll
        for (int kk = 0; kk < 4; kk++) {
            ph[kk][0] = packh2(__float2half_rn(s[2*kk][0]),   __float2half_rn(s[2*kk][1]));
            ph[kk][1] = packh2(__float2half_rn(s[2*kk][2]),   __float2half_rn(s[2*kk][3]));
            ph[kk][2] = packh2(__float2half_rn(s[2*kk+1][0]), __float2half_rn(s[2*kk+1][1]));
            ph[kk][3] = packh2(__float2half_rn(s[2*kk+1][2]), __float2half_rn(s[2*kk+1][3]));
        }

        // ---- O += P V (1-term) ----
        #pragma unroll
        for (int kk = 0; kk < 4; kk++) {
            #pragma unroll
            for (int p = 0; p < 4; p++) {
                uint32_t offv = (uint32_t)((kk * 16 + lrow) * FSTR + p * 16 + lkad) * 2;
                uint32_t rv[4];
                ldsm4t(rv, sVh + offv);
                mma_f16(o[2*p],   ph[kk], rv[0], rv[1]);
                mma_f16(o[2*p+1], ph[kk], rv[2], rv[3]);
            }
        }
    }

    // ---- epilogue: normalize, split fp16 hi/lo, write [B,T,C] ----
    const float inv0 = 1.f / l0_;
    const float inv1 = 1.f / l1_;
    const int t0 = qt * 128 + w * 16 + (l >> 2);
    #pragma unroll
    for (int nf = 0; nf < 8; nf++) {
        int col = hh * 64 + nf * 8 + (l & 3) * 2;
        #pragma unroll
        for (int hf = 0; hf < 2; hf++) {
            int t = t0 + hf * 8;
            float f0 = o[nf][hf*2 + 0] * (hf ? inv1 : inv0);
            float f1 = o[nf][hf*2 + 1] * (hf ? inv1 : inv0);
            __half h0 = __float2half_rn(f0), h1 = __float2half_rn(f1);
            size_t idx = ((size_t)(b * TT + t) << 10) + col;
            *(__half2*)&g_yh[idx] = __halves2half2(h0, h1);
            *(__half2*)&g_yl[idx] = __halves2half2(
                __float2half_rn(f0 - __half2float(h0)),
                __float2half_rn(f1 - __half2float(h1)));
        }
    }
}

// ---------------------------------------------------------------------------
extern "C" void kernel_launch(void* const* d_in, const int* in_sizes, int n_in,
                              void* d_out, int out_size)
{
    const float* x  = (const float*)d_in[0];
    const float* Wq = (const float*)d_in[1];
    const float* Wk = (const float*)d_in[2];
    const float* Wv = (const float*)d_in[3];
    const float* Wp = (const float*)d_in[4];
    float* out = (float*)d_out;

    cudaFuncSetAttribute(gemm_qkv,  cudaFuncAttributeMaxDynamicSharedMemorySize, GSMEM);
    cudaFuncSetAttribute(gemm_proj, cudaFuncAttributeMaxDynamicSharedMemorySize, GSMEM);
    cudaFuncSetAttribute(flash_mma, cudaFuncAttributeMaxDynamicSharedMemorySize, FSMEM);

    size_t total_pairs = XPAIRS + 4 * WPAIRS;   // 6M
    cvt_inputs<<<(unsigned)((total_pairs + 255) / 256), 256>>>(x, Wq, Wk, Wv, Wp);

    gemm_qkv<<<dim3(CC/128, MM/128, 3), 256, GSMEM>>>();
    flash_mma<<<dim3(TT/128, BB*HH), 256, FSMEM>>>();
    gemm_proj<<<dim3(CC/128, MM/128), 256, GSMEM>>>(out);
}

// round 9
// speedup vs baseline: 5.8826x; 1.1166x over previous
#include <cuda_runtime.h>
#include <cuda_fp16.h>
#include <cstdint>

#define BB 4
#define TT 2048
#define CC 1024
#define HH 16
#define DD 64
#define MM (BB*TT)   // 8192

// ---------------------------------------------------------------------------
// Scratch (device globals, 16B aligned)
// ---------------------------------------------------------------------------
__device__ __align__(16) __half g_xh[(size_t)MM*CC];
__device__ __align__(16) __half g_xl[(size_t)MM*CC];
__device__ __align__(16) __half g_wh[(size_t)4*CC*CC];   // q,k,v,p (hi only)
__device__ __align__(16) __half g_qh[(size_t)MM*CC];     // [B,H,T,D]
__device__ __align__(16) __half g_ql[(size_t)MM*CC];
__device__ __align__(16) __half g_kh[(size_t)MM*CC];
__device__ __align__(16) __half g_vh[(size_t)MM*CC];
__device__ __align__(16) __half g_yh[(size_t)MM*CC];     // [B,T,C]
__device__ __align__(16) __half g_yl[(size_t)MM*CC];

// ---------------------------------------------------------------------------
// PTX helpers
// ---------------------------------------------------------------------------
__device__ __forceinline__ uint32_t smem_u32(const void* p) {
    uint32_t a;
    asm("{ .reg .u64 t; cvta.to.shared.u64 t, %1; cvt.u32.u64 %0, t; }"
        : "=r"(a) : "l"(p));
    return a;
}
__device__ __forceinline__ void cp16(uint32_t dst, const void* src) {
    asm volatile("cp.async.cg.shared.global [%0], [%1], 16;" :: "r"(dst), "l"(src));
}
__device__ __forceinline__ void cp_commit() {
    asm volatile("cp.async.commit_group;" ::: "memory");
}
template<int N> __device__ __forceinline__ void cp_wait() {
    asm volatile("cp.async.wait_group %0;" :: "n"(N) : "memory");
}
__device__ __forceinline__ void ldsm4(uint32_t* r, uint32_t a) {
    asm volatile("ldmatrix.sync.aligned.m8n8.x4.shared.b16 {%0,%1,%2,%3}, [%4];"
        : "=r"(r[0]), "=r"(r[1]), "=r"(r[2]), "=r"(r[3]) : "r"(a));
}
__device__ __forceinline__ void ldsm4t(uint32_t* r, uint32_t a) {
    asm volatile("ldmatrix.sync.aligned.m8n8.x4.trans.shared.b16 {%0,%1,%2,%3}, [%4];"
        : "=r"(r[0]), "=r"(r[1]), "=r"(r[2]), "=r"(r[3]) : "r"(a));
}
__device__ __forceinline__ void mma_f16(float* d, const uint32_t* a, uint32_t b0, uint32_t b1) {
    asm volatile(
        "mma.sync.aligned.m16n8k16.row.col.f32.f16.f16.f32 "
        "{%0,%1,%2,%3}, {%4,%5,%6,%7}, {%8,%9}, {%0,%1,%2,%3};"
        : "+f"(d[0]), "+f"(d[1]), "+f"(d[2]), "+f"(d[3])
        : "r"(a[0]), "r"(a[1]), "r"(a[2]), "r"(a[3]), "r"(b0), "r"(b1));
}
__device__ __forceinline__ uint32_t packh2(__half a, __half b) {
    __half2 h = __halves2half2(a, b);
    return *(uint32_t*)&h;
}

// ---------------------------------------------------------------------------
// Fused conversion: x -> fp16 hi/lo, W{q,k,v,p} -> fp16 hi. 2 elems/thread.
// ---------------------------------------------------------------------------
#define XPAIRS ((size_t)MM*CC/2)     // 4194304
#define WPAIRS ((size_t)CC*CC/2)     // 524288

__global__ void cvt_inputs(const float* __restrict__ x,
                           const float* __restrict__ Wq, const float* __restrict__ Wk,
                           const float* __restrict__ Wv, const float* __restrict__ Wp) {
    size_t i = (size_t)blockIdx.x * blockDim.x + threadIdx.x;
    if (i < XPAIRS) {
        float2 v = ((const float2*)x)[i];
        __half h0 = __float2half_rn(v.x), h1 = __float2half_rn(v.y);
        ((__half2*)g_xh)[i] = __halves2half2(h0, h1);
        ((__half2*)g_xl)[i] = __halves2half2(
            __float2half_rn(v.x - __half2float(h0)),
            __float2half_rn(v.y - __half2float(h1)));
    } else {
        size_t j = i - XPAIRS;
        int which = (int)(j >> 19);
        size_t wi = j & (WPAIRS - 1);
        const float* src = (which == 0) ? Wq : (which == 1) ? Wk : (which == 2) ? Wv : Wp;
        float2 v = ((const float2*)src)[wi];
        ((__half2*)g_wh)[(size_t)which * WPAIRS + wi] =
            __halves2half2(__float2half_rn(v.x), __float2half_rn(v.y));
    }
}

// ---------------------------------------------------------------------------
// GEMM: C[64x128] = (Ah+Al) * Wh^T, fp16 2-term.
// 128 threads = 4 warps (1m x 4n), warp tile 64x32, 4 CTAs/SM.
// smem: 2 stages x (Ah 64x32, Al 64x32, Bh 128x32) fp16, row stride 40.
// ---------------------------------------------------------------------------
#define GSTR 40
#define GA_ELEMS (64*GSTR)           // 2560 elems per A tile
#define GB_ELEMS (128*GSTR)          // 5120 elems per B tile
#define GSTAGE_B ((2*GA_ELEMS + GB_ELEMS)*2)   // 20480 bytes per stage
#define GSMEM (2*GSTAGE_B)           // 40960

__device__ __forceinline__ void gemm_issue(
    uint32_t sb, int stage,
    const __half* __restrict__ Ah, const __half* __restrict__ Al,
    const __half* __restrict__ Bh, int m0, int n0, int k0)
{
    const int t = threadIdx.x;
    const uint32_t stb = sb + stage * GSTAGE_B;
    // A hi: 256 cp16 (64 rows x 4)
    #pragma unroll
    for (int i = 0; i < 2; i++) {
        int idx = i * 128 + t;
        int row = idx >> 2, c16 = idx & 3;
        cp16(stb + (uint32_t)(row * GSTR + c16 * 8) * 2,
             Ah + (size_t)(m0 + row) * CC + k0 + c16 * 8);
    }
    // A lo
    #pragma unroll
    for (int i = 0; i < 2; i++) {
        int idx = i * 128 + t;
        int row = idx >> 2, c16 = idx & 3;
        cp16(stb + (uint32_t)(GA_ELEMS + row * GSTR + c16 * 8) * 2,
             Al + (size_t)(m0 + row) * CC + k0 + c16 * 8);
    }
    // B hi: 512 cp16 (128 rows x 4)
    #pragma unroll
    for (int i = 0; i < 4; i++) {
        int idx = i * 128 + t;
        int row = idx >> 2, c16 = idx & 3;
        cp16(stb + (uint32_t)(2 * GA_ELEMS + row * GSTR + c16 * 8) * 2,
             Bh + (size_t)(n0 + row) * CC + k0 + c16 * 8);
    }
}

__device__ __forceinline__ void gemm_body(
    const __half* __restrict__ Ah, const __half* __restrict__ Al,
    const __half* __restrict__ Bh,
    int m0, int n0, uint32_t sb, float acc[4][4][4])
{
    const int l  = threadIdx.x & 31;
    const int wn = threadIdx.x >> 5;     // 0..3

    #pragma unroll
    for (int mf = 0; mf < 4; mf++)
        #pragma unroll
        for (int nf = 0; nf < 4; nf++)
            #pragma unroll
            for (int q = 0; q < 4; q++) acc[mf][nf][q] = 0.f;

    gemm_issue(sb, 0, Ah, Al, Bh, m0, n0, 0);
    cp_commit();

    const uint32_t lrow = (l & 15);
    const uint32_t lkad = ((l >> 4) << 3);

    #pragma unroll 1
    for (int c = 0; c < 32; c++) {
        cp_wait<0>();            // chunk c landed
        __syncthreads();         // all 4 warps done with chunk c-1 -> stage free
        if (c + 1 < 32)
            gemm_issue(sb, (c + 1) & 1, Ah, Al, Bh, m0, n0, (c + 1) * 32);
        cp_commit();             // uniform group count

        const uint32_t stb = sb + (c & 1) * GSTAGE_B;
        const uint32_t tAh = stb;
        const uint32_t tAl = stb + GA_ELEMS * 2;
        const uint32_t tBh = stb + 2 * GA_ELEMS * 2;

        #pragma unroll
        for (int ks = 0; ks < 32; ks += 16) {
            uint32_t ah[4][4], al[4][4];
            #pragma unroll
            for (int mf = 0; mf < 4; mf++) {
                uint32_t off = (uint32_t)((mf * 16 + lrow) * GSTR + ks + lkad) * 2;
                ldsm4(ah[mf], tAh + off);
                ldsm4(al[mf], tAl + off);
            }
            uint32_t bh[4][2];
            #pragma unroll
            for (int p = 0; p < 2; p++) {
                uint32_t off = (uint32_t)((wn * 32 + p * 16 + lrow) * GSTR + ks + lkad) * 2;
                uint32_t r[4];
                ldsm4(r, tBh + off);
                bh[2*p][0]   = r[0]; bh[2*p][1]   = r[2];
                bh[2*p+1][0] = r[1]; bh[2*p+1][1] = r[3];
            }
            #pragma unroll
            for (int mf = 0; mf < 4; mf++)
                #pragma unroll
                for (int nf = 0; nf < 4; nf++)
                    mma_f16(acc[mf][nf], ah[mf], bh[nf][0], bh[nf][1]);
            #pragma unroll
            for (int mf = 0; mf < 4; mf++)
                #pragma unroll
                for (int nf = 0; nf < 4; nf++)
                    mma_f16(acc[mf][nf], al[mf], bh[nf][0], bh[nf][1]);
        }
    }
}

// QKV projection: grid (8, 128, 3). q -> hi/lo fp16, k/v -> single fp16. [B,H,T,D]
__global__ __launch_bounds__(128, 4)
void gemm_qkv() {
    extern __shared__ __align__(16) char gsm[];
    const uint32_t sb = smem_u32(gsm);
    const int which = blockIdx.z;
    const int m0 = blockIdx.y * 64;
    const int n0 = blockIdx.x * 128;
    const __half* Wh = g_wh + (size_t)which * CC * CC;

    float acc[4][4][4];
    gemm_body(g_xh, g_xl, Wh, m0, n0, sb, acc);

    const int l  = threadIdx.x & 31;
    const int wn = threadIdx.x >> 5;

    #pragma unroll
    for (int mf = 0; mf < 4; mf++) {
        #pragma unroll
        for (int nf = 0; nf < 4; nf++) {
            int col = n0 + wn * 32 + nf * 8 + (l & 3) * 2;
            int hh = col >> 6, d = col & 63;
            #pragma unroll
            for (int hf = 0; hf < 2; hf++) {
                int m = m0 + mf * 16 + (l >> 2) + hf * 8;
                int b = m >> 11, t = m & (TT - 1);
                size_t idx = (((size_t)(b * HH + hh) * TT + t) << 6) + d;
                float f0 = acc[mf][nf][hf*2 + 0];
                float f1 = acc[mf][nf][hf*2 + 1];
                __half h0 = __float2half_rn(f0), h1 = __float2half_rn(f1);
                if (which == 0) {
                    *(__half2*)&g_qh[idx] = __halves2half2(h0, h1);
                    *(__half2*)&g_ql[idx] = __halves2half2(
                        __float2half_rn(f0 - __half2float(h0)),
                        __float2half_rn(f1 - __half2float(h1)));
                } else if (which == 1) {
                    *(__half2*)&g_kh[idx] = __halves2half2(h0, h1);
                } else {
                    *(__half2*)&g_vh[idx] = __halves2half2(h0, h1);
                }
            }
        }
    }
}

// Output projection: grid (8, 128); fp32 out
__global__ __launch_bounds__(128, 4)
void gemm_proj(float* __restrict__ out) {
    extern __shared__ __align__(16) char gsm[];
    const uint32_t sb = smem_u32(gsm);
    const int m0 = blockIdx.y * 64;
    const int n0 = blockIdx.x * 128;
    const __half* Wh = g_wh + (size_t)3 * CC * CC;

    float acc[4][4][4];
    gemm_body(g_yh, g_yl, Wh, m0, n0, sb, acc);

    const int l  = threadIdx.x & 31;
    const int wn = threadIdx.x >> 5;

    #pragma unroll
    for (int mf = 0; mf < 4; mf++)
        #pragma unroll
        for (int nf = 0; nf < 4; nf++) {
            int col = n0 + wn * 32 + nf * 8 + (l & 3) * 2;
            #pragma unroll
            for (int hf = 0; hf < 2; hf++) {
                int m = m0 + mf * 16 + (l >> 2) + hf * 8;
                *(float2*)&out[(size_t)m * CC + col] =
                    make_float2(acc[mf][nf][hf*2 + 0], acc[mf][nf][hf*2 + 1]);
            }
        }
}

// ---------------------------------------------------------------------------
// Flash attention. grid (32, 64), 128 thr (4 warps). BR=64 (16/warp), BC=64.
// QK^T: (Qh+Ql)*Kh (2-term). PV: P*Vh (1-term). KV 2-stage cp.async ring.
// 4 CTAs/SM.
// ---------------------------------------------------------------------------
#define FSTR 72
#define FKV_T (64*FSTR)              // 4608 elems per KV tile
#define FKV_STAGE_B (2*FKV_T*2)      // 18432 bytes per stage (Kh, Vh)
#define FQ_T (64*FSTR)               // 4608 elems per Q tile
#define FQ_OFF (2*FKV_STAGE_B)       // 36864
#define FSMEM (FQ_OFF + 2*FQ_T*2)    // 55296

__device__ __forceinline__ void kv_issue(uint32_t sb, int stage, size_t hb, int jt) {
    const int t = threadIdx.x;
    const uint32_t stb = sb + stage * FKV_STAGE_B;
    #pragma unroll
    for (int i = 0; i < 8; i++) {
        const int tile = i >> 2;                 // 0=K, 1=V
        int idx = ((i & 3) << 7) | t;            // 0..511
        int row = idx >> 3;
        int c16 = idx & 7;
        size_t go = hb + (size_t)(jt * 64 + row) * DD + c16 * 8;
        const __half* src = (tile == 0) ? (g_kh + go) : (g_vh + go);
        cp16(stb + (uint32_t)(tile * FKV_T + row * FSTR + c16 * 8) * 2, src);
    }
}

__global__ __launch_bounds__(128, 4)
void flash_mma() {
    extern __shared__ __align__(16) char fsm[];
    const uint32_t sb = smem_u32(fsm);

    const int tid = threadIdx.x;
    const int l   = tid & 31;
    const int w   = tid >> 5;            // 0..3
    const int qt  = (int)(gridDim.x - 1 - blockIdx.x);
    const int bh  = blockIdx.y;
    const int b   = bh >> 4;
    const int hh  = bh & 15;
    const size_t hb = (size_t)bh * TT * DD;
    const int ntile = qt + 1;

    // Q load (hi/lo) + kv0 in one group
    #pragma unroll
    for (int i = 0; i < 8; i++) {
        const int tile = i >> 2;                 // 0=hi, 1=lo
        int idx = ((i & 3) << 7) | tid;          // 0..511
        int row = idx >> 3;
        int c16 = idx & 7;
        const __half* src = (tile == 0 ? g_qh : g_ql) + hb + (size_t)(qt * 64 + row) * DD + c16 * 8;
        cp16(sb + FQ_OFF + (uint32_t)(tile * FQ_T + row * FSTR + c16 * 8) * 2, src);
    }
    kv_issue(sb, 0, hb, 0);
    cp_commit();

    float s[8][4], o[8][4];
    float m0_ = -1e30f, m1_ = -1e30f, l0_ = 0.f, l1_ = 0.f;
    #pragma unroll
    for (int nf = 0; nf < 8; nf++)
        #pragma unroll
        for (int q = 0; q < 4; q++) o[nf][q] = 0.f;

    const uint32_t sQh = sb + FQ_OFF;
    const uint32_t sQl = sQh + FQ_T * 2;
    const uint32_t lrow = (l & 15);
    const uint32_t lkad = ((l >> 4) << 3);

    #pragma unroll 1
    for (int jt = 0; jt < ntile; jt++) {
        cp_wait<0>();            // kv tile jt (and Q on jt=0) landed
        __syncthreads();         // 4 warps done with tile jt-1
        if (jt + 1 < ntile)
            kv_issue(sb, (jt + 1) & 1, hb, jt + 1);
        cp_commit();             // uniform group count

        const uint32_t kvb = sb + (jt & 1) * FKV_STAGE_B;
        const uint32_t sKh = kvb;
        const uint32_t sVh = kvb + FKV_T * 2;

        // ---- S = Q K^T (2-term, hi sweep then lo sweep) ----
        #pragma unroll
        for (int nf = 0; nf < 8; nf++)
            #pragma unroll
            for (int q = 0; q < 4; q++) s[nf][q] = 0.f;

        #pragma unroll
        for (int kd = 0; kd < 4; kd++) {
            uint32_t qh[4], ql[4];
            uint32_t offq = (uint32_t)((w * 16 + lrow) * FSTR + kd * 16 + lkad) * 2;
            ldsm4(qh, sQh + offq);
            ldsm4(ql, sQl + offq);
            uint32_t rk[4][4];
            #pragma unroll
            for (int p = 0; p < 4; p++) {
                uint32_t offk = (uint32_t)((p * 16 + lrow) * FSTR + kd * 16 + lkad) * 2;
                ldsm4(rk[p], sKh + offk);
            }
            #pragma unroll
            for (int p = 0; p < 4; p++) {
                mma_f16(s[2*p],   qh, rk[p][0], rk[p][2]);
                mma_f16(s[2*p+1], qh, rk[p][1], rk[p][3]);
            }
            #pragma unroll
            for (int p = 0; p < 4; p++) {
                mma_f16(s[2*p],   ql, rk[p][0], rk[p][2]);
                mma_f16(s[2*p+1], ql, rk[p][1], rk[p][3]);
            }
        }

        // ---- scale + causal mask ----
        const int row_lo = qt * 64 + w * 16 + (l >> 2);
        const int row_hi = row_lo + 8;
        const int col0 = jt * 64 + (l & 3) * 2;
        #pragma unroll
        for (int nf = 0; nf < 8; nf++)
            #pragma unroll
            for (int q = 0; q < 4; q++) s[nf][q] *= 0.125f;
        if (jt == qt) {
            #pragma unroll
            for (int nf = 0; nf < 8; nf++) {
                int c = col0 + nf * 8;
                if (c     > row_lo) s[nf][0] = -1e30f;
                if (c + 1 > row_lo) s[nf][1] = -1e30f;
                if (c     > row_hi) s[nf][2] = -1e30f;
                if (c + 1 > row_hi) s[nf][3] = -1e30f;
            }
        }

        // ---- online softmax ----
        float mt0 = -1e30f, mt1 = -1e30f;
        #pragma unroll
        for (int nf = 0; nf < 8; nf++) {
            mt0 = fmaxf(mt0, fmaxf(s[nf][0], s[nf][1]));
            mt1 = fmaxf(mt1, fmaxf(s[nf][2], s[nf][3]));
        }
        mt0 = fmaxf(mt0, __shfl_xor_sync(0xffffffffu, mt0, 1));
        mt0 = fmaxf(mt0, __shfl_xor_sync(0xffffffffu, mt0, 2));
        mt1 = fmaxf(mt1, __shfl_xor_sync(0xffffffffu, mt1, 1));
        mt1 = fmaxf(mt1, __shfl_xor_sync(0xffffffffu, mt1, 2));
        float mn0 = fmaxf(m0_, mt0);
        float mn1 = fmaxf(m1_, mt1);
        float cr0 = __expf(m0_ - mn0);
        float cr1 = __expf(m1_ - mn1);
        float rs0 = 0.f, rs1 = 0.f;
        #pragma unroll
        for (int nf = 0; nf < 8; nf++) {
            s[nf][0] = __expf(s[nf][0] - mn0);
            s[nf][1] = __expf(s[nf][1] - mn0);
            s[nf][2] = __expf(s[nf][2] - mn1);
            s[nf][3] = __expf(s[nf][3] - mn1);
            rs0 += s[nf][0] + s[nf][1];
            rs1 += s[nf][2] + s[nf][3];
        }
        rs0 += __shfl_xor_sync(0xffffffffu, rs0, 1);
        rs0 += __shfl_xor_sync(0xffffffffu, rs0, 2);
        rs1 += __shfl_xor_sync(0xffffffffu, rs1, 1);
        rs1 += __shfl_xor_sync(0xffffffffu, rs1, 2);
        l0_ = l0_ * cr0 + rs0;
        l1_ = l1_ * cr1 + rs1;
        m0_ = mn0; m1_ = mn1;
        #pragma unroll
        for (int nf = 0; nf < 8; nf++) {
            o[nf][0] *= cr0; o[nf][1] *= cr0;
            o[nf][2] *= cr1; o[nf][3] *= cr1;
        }

        // ---- P fragments (fp16) ----
        uint32_t ph[4][4];
        #pragma unroll
        for (int kk = 0; kk < 4; kk++) {
            ph[kk][0] = packh2(__float2half_rn(s[2*kk][0]),   __float2half_rn(s[2*kk][1]));
            ph[kk][1] = packh2(__float2half_rn(s[2*kk][2]),   __float2half_rn(s[2*kk][3]));
            ph[kk][2] = packh2(__float2half_rn(s[2*kk+1][0]), __float2half_rn(s[2*kk+1][1]));
            ph[kk][3] = packh2(__float2half_rn(s[2*kk+1][2]), __float2half_rn(s[2*kk+1][3]));
        }

        // ---- O += P V (1-term) ----
        #pragma unroll
        for (int kk = 0; kk < 4; kk++) {
            #pragma unroll
            for (int p = 0; p < 4; p++) {
                uint32_t offv = (uint32_t)((kk * 16 + lrow) * FSTR + p * 16 + lkad) * 2;
                uint32_t rv[4];
                ldsm4t(rv, sVh + offv);
                mma_f16(o[2*p],   ph[kk], rv[0], rv[1]);
                mma_f16(o[2*p+1], ph[kk], rv[2], rv[3]);
            }
        }
    }

    // ---- epilogue: normalize, split fp16 hi/lo, write [B,T,C] ----
    const float inv0 = 1.f / l0_;
    const float inv1 = 1.f / l1_;
    const int t0 = qt * 64 + w * 16 + (l >> 2);
    #pragma unroll
    for (int nf = 0; nf < 8; nf++) {
        int col = hh * 64 + nf * 8 + (l & 3) * 2;
        #pragma unroll
        for (int hf = 0; hf < 2; hf++) {
            int t = t0 + hf * 8;
            float f0 = o[nf][hf*2 + 0] * (hf ? inv1 : inv0);
            float f1 = o[nf][hf*2 + 1] * (hf ? inv1 : inv0);
            __half h0 = __float2half_rn(f0), h1 = __float2half_rn(f1);
            size_t idx = ((size_t)(b * TT + t) << 10) + col;
            *(__half2*)&g_yh[idx] = __halves2half2(h0, h1);
            *(__half2*)&g_yl[idx] = __halves2half2(
                __float2half_rn(f0 - __half2float(h0)),
                __float2half_rn(f1 - __half2float(h1)));
        }
    }
}

// ---------------------------------------------------------------------------
extern "C" void kernel_launch(void* const* d_in, const int* in_sizes, int n_in,
                              void* d_out, int out_size)
{
    const float* x  = (const float*)d_in[0];
    const float* Wq = (const float*)d_in[1];
    const float* Wk = (const float*)d_in[2];
    const float* Wv = (const float*)d_in[3];
    const float* Wp = (const float*)d_in[4];
    float* out = (float*)d_out;

    cudaFuncSetAttribute(gemm_qkv,  cudaFuncAttributeMaxDynamicSharedMemorySize, GSMEM);
    cudaFuncSetAttribute(gemm_proj, cudaFuncAttributeMaxDynamicSharedMemorySize, GSMEM);
    cudaFuncSetAttribute(flash_mma, cudaFuncAttributeMaxDynamicSharedMemorySize, FSMEM);

    size_t total_pairs = XPAIRS + 4 * WPAIRS;   // 6M
    cvt_inputs<<<(unsigned)((total_pairs + 255) / 256), 256>>>(x, Wq, Wk, Wv, Wp);

    gemm_qkv<<<dim3(CC/128, MM/64, 3), 128, GSMEM>>>();
    flash_mma<<<dim3(TT/64, BB*HH), 128, FSMEM>>>();
    gemm_proj<<<dim3(CC/128, MM/64), 128, GSMEM>>>(out);
}

// round 10
// speedup vs baseline: 7.3796x; 1.2545x over previous
#include <cuda_runtime.h>
#include <cuda_fp16.h>
#include <cstdint>

#define BB 4
#define TT 2048
#define CC 1024
#define HH 16
#define DD 64
#define MM (BB*TT)   // 8192

// ---------------------------------------------------------------------------
// Scratch (device globals, 16B aligned)
// ---------------------------------------------------------------------------
__device__ __align__(16) __half g_xh[(size_t)MM*CC];
__device__ __align__(16) __half g_xl[(size_t)MM*CC];
__device__ __align__(16) __half g_wh[(size_t)4*CC*CC];   // q,k,v,p (hi only)
__device__ __align__(16) __half g_qh[(size_t)MM*CC];     // [B,H,T,D]
__device__ __align__(16) __half g_ql[(size_t)MM*CC];
__device__ __align__(16) __half g_kh[(size_t)MM*CC];
__device__ __align__(16) __half g_vh[(size_t)MM*CC];
__device__ __align__(16) __half g_yh[(size_t)MM*CC];     // [B,T,C]

// ---------------------------------------------------------------------------
// PTX helpers
// ---------------------------------------------------------------------------
__device__ __forceinline__ uint32_t smem_u32(const void* p) {
    uint32_t a;
    asm("{ .reg .u64 t; cvta.to.shared.u64 t, %1; cvt.u32.u64 %0, t; }"
        : "=r"(a) : "l"(p));
    return a;
}
__device__ __forceinline__ void cp16(uint32_t dst, const void* src) {
    asm volatile("cp.async.cg.shared.global [%0], [%1], 16;" :: "r"(dst), "l"(src));
}
__device__ __forceinline__ void cp_commit() {
    asm volatile("cp.async.commit_group;" ::: "memory");
}
template<int N> __device__ __forceinline__ void cp_wait() {
    asm volatile("cp.async.wait_group %0;" :: "n"(N) : "memory");
}
__device__ __forceinline__ void ldsm4(uint32_t* r, uint32_t a) {
    asm volatile("ldmatrix.sync.aligned.m8n8.x4.shared.b16 {%0,%1,%2,%3}, [%4];"
        : "=r"(r[0]), "=r"(r[1]), "=r"(r[2]), "=r"(r[3]) : "r"(a));
}
__device__ __forceinline__ void ldsm4t(uint32_t* r, uint32_t a) {
    asm volatile("ldmatrix.sync.aligned.m8n8.x4.trans.shared.b16 {%0,%1,%2,%3}, [%4];"
        : "=r"(r[0]), "=r"(r[1]), "=r"(r[2]), "=r"(r[3]) : "r"(a));
}
__device__ __forceinline__ void mma_f16(float* d, const uint32_t* a, uint32_t b0, uint32_t b1) {
    asm volatile(
        "mma.sync.aligned.m16n8k16.row.col.f32.f16.f16.f32 "
        "{%0,%1,%2,%3}, {%4,%5,%6,%7}, {%8,%9}, {%0,%1,%2,%3};"
        : "+f"(d[0]), "+f"(d[1]), "+f"(d[2]), "+f"(d[3])
        : "r"(a[0]), "r"(a[1]), "r"(a[2]), "r"(a[3]), "r"(b0), "r"(b1));
}
__device__ __forceinline__ uint32_t packh2(__half a, __half b) {
    __half2 h = __halves2half2(a, b);
    return *(uint32_t*)&h;
}

// ---------------------------------------------------------------------------
// Fused conversion: x -> fp16 hi/lo, W{q,k,v,p} -> fp16 hi. 2 elems/thread.
// ---------------------------------------------------------------------------
#define XPAIRS ((size_t)MM*CC/2)     // 4194304
#define WPAIRS ((size_t)CC*CC/2)     // 524288

__global__ void cvt_inputs(const float* __restrict__ x,
                           const float* __restrict__ Wq, const float* __restrict__ Wk,
                           const float* __restrict__ Wv, const float* __restrict__ Wp) {
    size_t i = (size_t)blockIdx.x * blockDim.x + threadIdx.x;
    if (i < XPAIRS) {
        float2 v = ((const float2*)x)[i];
        __half h0 = __float2half_rn(v.x), h1 = __float2half_rn(v.y);
        ((__half2*)g_xh)[i] = __halves2half2(h0, h1);
        ((__half2*)g_xl)[i] = __halves2half2(
            __float2half_rn(v.x - __half2float(h0)),
            __float2half_rn(v.y - __half2float(h1)));
    } else {
        size_t j = i - XPAIRS;
        int which = (int)(j >> 19);
        size_t wi = j & (WPAIRS - 1);
        const float* src = (which == 0) ? Wq : (which == 1) ? Wk : (which == 2) ? Wv : Wp;
        float2 v = ((const float2*)src)[wi];
        ((__half2*)g_wh)[(size_t)which * WPAIRS + wi] =
            __halves2half2(__float2half_rn(v.x), __float2half_rn(v.y));
    }
}

// ---------------------------------------------------------------------------
// GEMM: C[64x128] = A * Wh^T, fp16, templated 1-term (Ah) or 2-term (Ah+Al).
// 128 threads = 4 warps (1m x 4n), warp tile 64x32, 4 CTAs/SM.
// smem: 2 stages x (Ah 64x32 [, Al 64x32], Bh 128x32) fp16, row stride 40.
// ---------------------------------------------------------------------------
#define GSTR 40
#define GA_ELEMS (64*GSTR)           // 2560 elems per A tile
#define GB_ELEMS (128*GSTR)          // 5120 elems per B tile
#define GSTAGE_B ((2*GA_ELEMS + GB_ELEMS)*2)   // 20480 bytes per stage
#define GSMEM (2*GSTAGE_B)           // 40960

template<bool LO>
__device__ __forceinline__ void gemm_issue(
    uint32_t sb, int stage,
    const __half* __restrict__ Ah, const __half* __restrict__ Al,
    const __half* __restrict__ Bh, int m0, int n0, int k0)
{
    const int t = threadIdx.x;
    const uint32_t stb = sb + stage * GSTAGE_B;
    #pragma unroll
    for (int i = 0; i < 2; i++) {
        int idx = i * 128 + t;
        int row = idx >> 2, c16 = idx & 3;
        cp16(stb + (uint32_t)(row * GSTR + c16 * 8) * 2,
             Ah + (size_t)(m0 + row) * CC + k0 + c16 * 8);
    }
    if (LO) {
        #pragma unroll
        for (int i = 0; i < 2; i++) {
            int idx = i * 128 + t;
            int row = idx >> 2, c16 = idx & 3;
            cp16(stb + (uint32_t)(GA_ELEMS + row * GSTR + c16 * 8) * 2,
                 Al + (size_t)(m0 + row) * CC + k0 + c16 * 8);
        }
    }
    #pragma unroll
    for (int i = 0; i < 4; i++) {
        int idx = i * 128 + t;
        int row = idx >> 2, c16 = idx & 3;
        cp16(stb + (uint32_t)(2 * GA_ELEMS + row * GSTR + c16 * 8) * 2,
             Bh + (size_t)(n0 + row) * CC + k0 + c16 * 8);
    }
}

template<bool LO>
__device__ __forceinline__ void gemm_body(
    const __half* __restrict__ Ah, const __half* __restrict__ Al,
    const __half* __restrict__ Bh,
    int m0, int n0, uint32_t sb, float acc[4][4][4])
{
    const int l  = threadIdx.x & 31;
    const int wn = threadIdx.x >> 5;     // 0..3

    #pragma unroll
    for (int mf = 0; mf < 4; mf++)
        #pragma unroll
        for (int nf = 0; nf < 4; nf++)
            #pragma unroll
            for (int q = 0; q < 4; q++) acc[mf][nf][q] = 0.f;

    gemm_issue<LO>(sb, 0, Ah, Al, Bh, m0, n0, 0);
    cp_commit();

    const uint32_t lrow = (l & 15);
    const uint32_t lkad = ((l >> 4) << 3);

    #pragma unroll 1
    for (int c = 0; c < 32; c++) {
        cp_wait<0>();            // chunk c landed
        __syncthreads();         // all 4 warps done with chunk c-1 -> stage free
        if (c + 1 < 32)
            gemm_issue<LO>(sb, (c + 1) & 1, Ah, Al, Bh, m0, n0, (c + 1) * 32);
        cp_commit();             // uniform group count

        const uint32_t stb = sb + (c & 1) * GSTAGE_B;
        const uint32_t tAh = stb;
        const uint32_t tAl = stb + GA_ELEMS * 2;
        const uint32_t tBh = stb + 2 * GA_ELEMS * 2;

        #pragma unroll
        for (int ks = 0; ks < 32; ks += 16) {
            uint32_t ah[4][4], al[4][4];
            #pragma unroll
            for (int mf = 0; mf < 4; mf++) {
                uint32_t off = (uint32_t)((mf * 16 + lrow) * GSTR + ks + lkad) * 2;
                ldsm4(ah[mf], tAh + off);
                if (LO) ldsm4(al[mf], tAl + off);
            }
            uint32_t bh[4][2];
            #pragma unroll
            for (int p = 0; p < 2; p++) {
                uint32_t off = (uint32_t)((wn * 32 + p * 16 + lrow) * GSTR + ks + lkad) * 2;
                uint32_t r[4];
                ldsm4(r, tBh + off);
                bh[2*p][0]   = r[0]; bh[2*p][1]   = r[2];
                bh[2*p+1][0] = r[1]; bh[2*p+1][1] = r[3];
            }
            #pragma unroll
            for (int mf = 0; mf < 4; mf++)
                #pragma unroll
                for (int nf = 0; nf < 4; nf++)
                    mma_f16(acc[mf][nf], ah[mf], bh[nf][0], bh[nf][1]);
            if (LO) {
                #pragma unroll
                for (int mf = 0; mf < 4; mf++)
                    #pragma unroll
                    for (int nf = 0; nf < 4; nf++)
                        mma_f16(acc[mf][nf], al[mf], bh[nf][0], bh[nf][1]);
            }
        }
    }
}

// Q projection (2-term): grid (8, 128). q -> hi/lo fp16 [B,H,T,D]
__global__ __launch_bounds__(128, 4)
void gemm_q() {
    extern __shared__ __align__(16) char gsm[];
    const uint32_t sb = smem_u32(gsm);
    const int m0 = blockIdx.y * 64;
    const int n0 = blockIdx.x * 128;

    float acc[4][4][4];
    gemm_body<true>(g_xh, g_xl, g_wh, m0, n0, sb, acc);

    const int l  = threadIdx.x & 31;
    const int wn = threadIdx.x >> 5;

    #pragma unroll
    for (int mf = 0; mf < 4; mf++) {
        #pragma unroll
        for (int nf = 0; nf < 4; nf++) {
            int col = n0 + wn * 32 + nf * 8 + (l & 3) * 2;
            int hh = col >> 6, d = col & 63;
            #pragma unroll
            for (int hf = 0; hf < 2; hf++) {
                int m = m0 + mf * 16 + (l >> 2) + hf * 8;
                int b = m >> 11, t = m & (TT - 1);
                size_t idx = (((size_t)(b * HH + hh) * TT + t) << 6) + d;
                float f0 = acc[mf][nf][hf*2 + 0];
                float f1 = acc[mf][nf][hf*2 + 1];
                __half h0 = __float2half_rn(f0), h1 = __float2half_rn(f1);
                *(__half2*)&g_qh[idx] = __halves2half2(h0, h1);
                *(__half2*)&g_ql[idx] = __halves2half2(
                    __float2half_rn(f0 - __half2float(h0)),
                    __float2half_rn(f1 - __half2float(h1)));
            }
        }
    }
}

// K/V projections (1-term): grid (8, 128, 2). single fp16 out [B,H,T,D]
__global__ __launch_bounds__(128, 4)
void gemm_kv() {
    extern __shared__ __align__(16) char gsm[];
    const uint32_t sb = smem_u32(gsm);
    const int which = blockIdx.z;            // 0=K, 1=V
    const int m0 = blockIdx.y * 64;
    const int n0 = blockIdx.x * 128;
    const __half* Wh = g_wh + (size_t)(which + 1) * CC * CC;

    float acc[4][4][4];
    gemm_body<false>(g_xh, nullptr, Wh, m0, n0, sb, acc);

    __half* dst = (which == 0) ? g_kh : g_vh;
    const int l  = threadIdx.x & 31;
    const int wn = threadIdx.x >> 5;

    #pragma unroll
    for (int mf = 0; mf < 4; mf++) {
        #pragma unroll
        for (int nf = 0; nf < 4; nf++) {
            int col = n0 + wn * 32 + nf * 8 + (l & 3) * 2;
            int hh = col >> 6, d = col & 63;
            #pragma unroll
            for (int hf = 0; hf < 2; hf++) {
                int m = m0 + mf * 16 + (l >> 2) + hf * 8;
                int b = m >> 11, t = m & (TT - 1);
                size_t idx = (((size_t)(b * HH + hh) * TT + t) << 6) + d;
                *(__half2*)&dst[idx] = __halves2half2(
                    __float2half_rn(acc[mf][nf][hf*2 + 0]),
                    __float2half_rn(acc[mf][nf][hf*2 + 1]));
            }
        }
    }
}

// Output projection (1-term): grid (8, 128); fp32 out
__global__ __launch_bounds__(128, 4)
void gemm_proj(float* __restrict__ out) {
    extern __shared__ __align__(16) char gsm[];
    const uint32_t sb = smem_u32(gsm);
    const int m0 = blockIdx.y * 64;
    const int n0 = blockIdx.x * 128;
    const __half* Wh = g_wh + (size_t)3 * CC * CC;

    float acc[4][4][4];
    gemm_body<false>(g_yh, nullptr, Wh, m0, n0, sb, acc);

    const int l  = threadIdx.x & 31;
    const int wn = threadIdx.x >> 5;

    #pragma unroll
    for (int mf = 0; mf < 4; mf++)
        #pragma unroll
        for (int nf = 0; nf < 4; nf++) {
            int col = n0 + wn * 32 + nf * 8 + (l & 3) * 2;
            #pragma unroll
            for (int hf = 0; hf < 2; hf++) {
                int m = m0 + mf * 16 + (l >> 2) + hf * 8;
                *(float2*)&out[(size_t)m * CC + col] =
                    make_float2(acc[mf][nf][hf*2 + 0], acc[mf][nf][hf*2 + 1]);
            }
        }
}

// ---------------------------------------------------------------------------
// Flash attention. grid (32, 64), 128 thr (4 warps). BR=64 (16/warp), BC=64.
// QK^T: (Qh+Ql)*Kh (2-term). PV: P*Vh (1-term). KV 2-stage cp.async ring.
// 4 CTAs/SM. Epilogue writes y as single fp16.
// ---------------------------------------------------------------------------
#define FSTR 72
#define FKV_T (64*FSTR)              // 4608 elems per KV tile
#define FKV_STAGE_B (2*FKV_T*2)      // 18432 bytes per stage (Kh, Vh)
#define FQ_T (64*FSTR)               // 4608 elems per Q tile
#define FQ_OFF (2*FKV_STAGE_B)       // 36864
#define FSMEM (FQ_OFF + 2*FQ_T*2)    // 55296

__device__ __forceinline__ void kv_issue(uint32_t sb, int stage, size_t hb, int jt) {
    const int t = threadIdx.x;
    const uint32_t stb = sb + stage * FKV_STAGE_B;
    #pragma unroll
    for (int i = 0; i < 8; i++) {
        const int tile = i >> 2;                 // 0=K, 1=V
        int idx = ((i & 3) << 7) | t;            // 0..511
        int row = idx >> 3;
        int c16 = idx & 7;
        size_t go = hb + (size_t)(jt * 64 + row) * DD + c16 * 8;
        const __half* src = (tile == 0) ? (g_kh + go) : (g_vh + go);
        cp16(stb + (uint32_t)(tile * FKV_T + row * FSTR + c16 * 8) * 2, src);
    }
}

__global__ __launch_bounds__(128, 4)
void flash_mma() {
    extern __shared__ __align__(16) char fsm[];
    const uint32_t sb = smem_u32(fsm);

    const int tid = threadIdx.x;
    const int l   = tid & 31;
    const int w   = tid >> 5;            // 0..3
    const int qt  = (int)(gridDim.x - 1 - blockIdx.x);
    const int bh  = blockIdx.y;
    const int b   = bh >> 4;
    const int hh  = bh & 15;
    const size_t hb = (size_t)bh * TT * DD;
    const int ntile = qt + 1;

    // Q load (hi/lo) + kv0 in one group
    #pragma unroll
    for (int i = 0; i < 8; i++) {
        const int tile = i >> 2;                 // 0=hi, 1=lo
        int idx = ((i & 3) << 7) | tid;          // 0..511
        int row = idx >> 3;
        int c16 = idx & 7;
        const __half* src = (tile == 0 ? g_qh : g_ql) + hb + (size_t)(qt * 64 + row) * DD + c16 * 8;
        cp16(sb + FQ_OFF + (uint32_t)(tile * FQ_T + row * FSTR + c16 * 8) * 2, src);
    }
    kv_issue(sb, 0, hb, 0);
    cp_commit();

    float s[8][4], o[8][4];
    float m0_ = -1e30f, m1_ = -1e30f, l0_ = 0.f, l1_ = 0.f;
    #pragma unroll
    for (int nf = 0; nf < 8; nf++)
        #pragma unroll
        for (int q = 0; q < 4; q++) o[nf][q] = 0.f;

    const uint32_t sQh = sb + FQ_OFF;
    const uint32_t sQl = sQh + FQ_T * 2;
    const uint32_t lrow = (l & 15);
    const uint32_t lkad = ((l >> 4) << 3);

    #pragma unroll 1
    for (int jt = 0; jt < ntile; jt++) {
        cp_wait<0>();            // kv tile jt (and Q on jt=0) landed
        __syncthreads();         // 4 warps done with tile jt-1
        if (jt + 1 < ntile)
            kv_issue(sb, (jt + 1) & 1, hb, jt + 1);
        cp_commit();             // uniform group count

        const uint32_t kvb = sb + (jt & 1) * FKV_STAGE_B;
        const uint32_t sKh = kvb;
        const uint32_t sVh = kvb + FKV_T * 2;

        // ---- S = Q K^T (2-term, hi sweep then lo sweep) ----
        #pragma unroll
        for (int nf = 0; nf < 8; nf++)
            #pragma unroll
            for (int q = 0; q < 4; q++) s[nf][q] = 0.f;

        #pragma unroll
        for (int kd = 0; kd < 4; kd++) {
            uint32_t qh[4], ql[4];
            uint32_t offq = (uint32_t)((w * 16 + lrow) * FSTR + kd * 16 + lkad) * 2;
            ldsm4(qh, sQh + offq);
            ldsm4(ql, sQl + offq);
            uint32_t rk[4][4];
            #pragma unroll
            for (int p = 0; p < 4; p++) {
                uint32_t offk = (uint32_t)((p * 16 + lrow) * FSTR + kd * 16 + lkad) * 2;
                ldsm4(rk[p], sKh + offk);
            }
            #pragma unroll
            for (int p = 0; p < 4; p++) {
                mma_f16(s[2*p],   qh, rk[p][0], rk[p][2]);
                mma_f16(s[2*p+1], qh, rk[p][1], rk[p][3]);
            }
            #pragma unroll
            for (int p = 0; p < 4; p++) {
                mma_f16(s[2*p],   ql, rk[p][0], rk[p][2]);
                mma_f16(s[2*p+1], ql, rk[p][1], rk[p][3]);
            }
        }

        // ---- scale + causal mask ----
        const int row_lo = qt * 64 + w * 16 + (l >> 2);
        const int row_hi = row_lo + 8;
        const int col0 = jt * 64 + (l & 3) * 2;
        #pragma unroll
        for (int nf = 0; nf < 8; nf++)
            #pragma unroll
            for (int q = 0; q < 4; q++) s[nf][q] *= 0.125f;
        if (jt == qt) {
            #pragma unroll
            for (int nf = 0; nf < 8; nf++) {
                int c = col0 + nf * 8;
                if (c     > row_lo) s[nf][0] = -1e30f;
                if (c + 1 > row_lo) s[nf][1] = -1e30f;
                if (c     > row_hi) s[nf][2] = -1e30f;
                if (c + 1 > row_hi) s[nf][3] = -1e30f;
            }
        }

        // ---- online softmax ----
        float mt0 = -1e30f, mt1 = -1e30f;
        #pragma unroll
        for (int nf = 0; nf < 8; nf++) {
            mt0 = fmaxf(mt0, fmaxf(s[nf][0], s[nf][1]));
            mt1 = fmaxf(mt1, fmaxf(s[nf][2], s[nf][3]));
        }
        mt0 = fmaxf(mt0, __shfl_xor_sync(0xffffffffu, mt0, 1));
        mt0 = fmaxf(mt0, __shfl_xor_sync(0xffffffffu, mt0, 2));
        mt1 = fmaxf(mt1, __shfl_xor_sync(0xffffffffu, mt1, 1));
        mt1 = fmaxf(mt1, __shfl_xor_sync(0xffffffffu, mt1, 2));
        float mn0 = fmaxf(m0_, mt0);
        float mn1 = fmaxf(m1_, mt1);
        float cr0 = __expf(m0_ - mn0);
        float cr1 = __expf(m1_ - mn1);
        float rs0 = 0.f, rs1 = 0.f;
        #pragma unroll
        for (int nf = 0; nf < 8; nf++) {
            s[nf][0] = __expf(s[nf][0] - mn0);
            s[nf][1] = __expf(s[nf][1] - mn0);
            s[nf][2] = __expf(s[nf][2] - mn1);
            s[nf][3] = __expf(s[nf][3] - mn1);
            rs0 += s[nf][0] + s[nf][1];
            rs1 += s[nf][2] + s[nf][3];
        }
        rs0 += __shfl_xor_sync(0xffffffffu, rs0, 1);
        rs0 += __shfl_xor_sync(0xffffffffu, rs0, 2);
        rs1 += __shfl_xor_sync(0xffffffffu, rs1, 1);
        rs1 += __shfl_xor_sync(0xffffffffu, rs1, 2);
        l0_ = l0_ * cr0 + rs0;
        l1_ = l1_ * cr1 + rs1;
        m0_ = mn0; m1_ = mn1;
        #pragma unroll
        for (int nf = 0; nf < 8; nf++) {
            o[nf][0] *= cr0; o[nf][1] *= cr0;
            o[nf][2] *= cr1; o[nf][3] *= cr1;
        }

        // ---- P fragments (fp16) ----
        uint32_t ph[4][4];
        #pragma unroll
        for (int kk = 0; kk < 4; kk++) {
            ph[kk][0] = packh2(__float2half_rn(s[2*kk][0]),   __float2half_rn(s[2*kk][1]));
            ph[kk][1] = packh2(__float2half_rn(s[2*kk][2]),   __float2half_rn(s[2*kk][3]));
            ph[kk][2] = packh2(__float2half_rn(s[2*kk+1][0]), __float2half_rn(s[2*kk+1][1]));
            ph[kk][3] = packh2(__float2half_rn(s[2*kk+1][2]), __float2half_rn(s[2*kk+1][3]));
        }

        // ---- O += P V (1-term) ----
        #pragma unroll
        for (int kk = 0; kk < 4; kk++) {
            #pragma unroll
            for (int p = 0; p < 4; p++) {
                uint32_t offv = (uint32_t)((kk * 16 + lrow) * FSTR + p * 16 + lkad) * 2;
                uint32_t rv[4];
                ldsm4t(rv, sVh + offv);
                mma_f16(o[2*p],   ph[kk], rv[0], rv[1]);
                mma_f16(o[2*p+1], ph[kk], rv[2], rv[3]);
            }
        }
    }

    // ---- epilogue: normalize, write y as fp16 [B,T,C] ----
    const float inv0 = 1.f / l0_;
    const float inv1 = 1.f / l1_;
    const int t0 = qt * 64 + w * 16 + (l >> 2);
    #pragma unroll
    for (int nf = 0; nf < 8; nf++) {
        int col = hh * 64 + nf * 8 + (l & 3) * 2;
        #pragma unroll
        for (int hf = 0; hf < 2; hf++) {
            int t = t0 + hf * 8;
            float f0 = o[nf][hf*2 + 0] * (hf ? inv1 : inv0);
            float f1 = o[nf][hf*2 + 1] * (hf ? inv1 : inv0);
            size_t idx = ((size_t)(b * TT + t) << 10) + col;
            *(__half2*)&g_yh[idx] = __halves2half2(
                __float2half_rn(f0), __float2half_rn(f1));
        }
    }
}

// ---------------------------------------------------------------------------
extern "C" void kernel_launch(void* const* d_in, const int* in_sizes, int n_in,
                              void* d_out, int out_size)
{
    const float* x  = (const float*)d_in[0];
    const float* Wq = (const float*)d_in[1];
    const float* Wk = (const float*)d_in[2];
    const float* Wv = (const float*)d_in[3];
    const float* Wp = (const float*)d_in[4];
    float* out = (float*)d_out;

    cudaFuncSetAttribute(gemm_q,    cudaFuncAttributeMaxDynamicSharedMemorySize, GSMEM);
    cudaFuncSetAttribute(gemm_kv,   cudaFuncAttributeMaxDynamicSharedMemorySize, GSMEM);
    cudaFuncSetAttribute(gemm_proj, cudaFuncAttributeMaxDynamicSharedMemorySize, GSMEM);
    cudaFuncSetAttribute(flash_mma, cudaFuncAttributeMaxDynamicSharedMemorySize, FSMEM);

    size_t total_pairs = XPAIRS + 4 * WPAIRS;   // 6M
    cvt_inputs<<<(unsigned)((total_pairs + 255) / 256), 256>>>(x, Wq, Wk, Wv, Wp);

    gemm_q<<<dim3(CC/128, MM/64), 128, GSMEM>>>();
    gemm_kv<<<dim3(CC/128, MM/64, 2), 128, GSMEM>>>();
    flash_mma<<<dim3(TT/64, BB*HH), 128, FSMEM>>>();
    gemm_proj<<<dim3(CC/128, MM/64), 128, GSMEM>>>(out);
}

// round 11
// speedup vs baseline: 7.4489x; 1.0094x over previous
#include <cuda_runtime.h>
#include <cuda_fp16.h>
#include <cstdint>

#define BB 4
#define TT 2048
#define CC 1024
#define HH 16
#define DD 64
#define MM (BB*TT)   // 8192

// logits pre-scale: 1/sqrt(D) * log2(e), folded into q at projection time
#define QSCALE 0.18033688011112042f

// ---------------------------------------------------------------------------
// Scratch (device globals, 16B aligned)
// ---------------------------------------------------------------------------
__device__ __align__(16) __half g_xh[(size_t)MM*CC];
__device__ __align__(16) __half g_xl[(size_t)MM*CC];
__device__ __align__(16) __half g_wh[(size_t)4*CC*CC];   // q,k,v,p (hi only)
__device__ __align__(16) __half g_qh[(size_t)MM*CC];     // [B,H,T,D] (pre-scaled)
__device__ __align__(16) __half g_ql[(size_t)MM*CC];
__device__ __align__(16) __half g_kh[(size_t)MM*CC];
__device__ __align__(16) __half g_vh[(size_t)MM*CC];
__device__ __align__(16) __half g_yh[(size_t)MM*CC];     // [B,T,C]

// ---------------------------------------------------------------------------
// PTX helpers
// ---------------------------------------------------------------------------
__device__ __forceinline__ uint32_t smem_u32(const void* p) {
    uint32_t a;
    asm("{ .reg .u64 t; cvta.to.shared.u64 t, %1; cvt.u32.u64 %0, t; }"
        : "=r"(a) : "l"(p));
    return a;
}
__device__ __forceinline__ void cp16(uint32_t dst, const void* src) {
    asm volatile("cp.async.cg.shared.global [%0], [%1], 16;" :: "r"(dst), "l"(src));
}
__device__ __forceinline__ void cp_commit() {
    asm volatile("cp.async.commit_group;" ::: "memory");
}
template<int N> __device__ __forceinline__ void cp_wait() {
    asm volatile("cp.async.wait_group %0;" :: "n"(N) : "memory");
}
__device__ __forceinline__ void ldsm4(uint32_t* r, uint32_t a) {
    asm volatile("ldmatrix.sync.aligned.m8n8.x4.shared.b16 {%0,%1,%2,%3}, [%4];"
        : "=r"(r[0]), "=r"(r[1]), "=r"(r[2]), "=r"(r[3]) : "r"(a));
}
__device__ __forceinline__ void ldsm4t(uint32_t* r, uint32_t a) {
    asm volatile("ldmatrix.sync.aligned.m8n8.x4.trans.shared.b16 {%0,%1,%2,%3}, [%4];"
        : "=r"(r[0]), "=r"(r[1]), "=r"(r[2]), "=r"(r[3]) : "r"(a));
}
__device__ __forceinline__ void mma_f16(float* d, const uint32_t* a, uint32_t b0, uint32_t b1) {
    asm volatile(
        "mma.sync.aligned.m16n8k16.row.col.f32.f16.f16.f32 "
        "{%0,%1,%2,%3}, {%4,%5,%6,%7}, {%8,%9}, {%0,%1,%2,%3};"
        : "+f"(d[0]), "+f"(d[1]), "+f"(d[2]), "+f"(d[3])
        : "r"(a[0]), "r"(a[1]), "r"(a[2]), "r"(a[3]), "r"(b0), "r"(b1));
}
__device__ __forceinline__ uint32_t pack2(float a, float b) {
    __half2 h = __float22half2_rn(make_float2(a, b));   // single F2FP.PACK
    return *(uint32_t*)&h;
}

// ---------------------------------------------------------------------------
// Fused conversion: x -> fp16 hi/lo, W{q,k,v,p} -> fp16 hi. 2 elems/thread.
// ---------------------------------------------------------------------------
#define XPAIRS ((size_t)MM*CC/2)     // 4194304
#define WPAIRS ((size_t)CC*CC/2)     // 524288

__global__ void cvt_inputs(const float* __restrict__ x,
                           const float* __restrict__ Wq, const float* __restrict__ Wk,
                           const float* __restrict__ Wv, const float* __restrict__ Wp) {
    size_t i = (size_t)blockIdx.x * blockDim.x + threadIdx.x;
    if (i < XPAIRS) {
        float2 v = ((const float2*)x)[i];
        __half h0 = __float2half_rn(v.x), h1 = __float2half_rn(v.y);
        ((__half2*)g_xh)[i] = __halves2half2(h0, h1);
        ((__half2*)g_xl)[i] = __halves2half2(
            __float2half_rn(v.x - __half2float(h0)),
            __float2half_rn(v.y - __half2float(h1)));
    } else {
        size_t j = i - XPAIRS;
        int which = (int)(j >> 19);
        size_t wi = j & (WPAIRS - 1);
        const float* src = (which == 0) ? Wq : (which == 1) ? Wk : (which == 2) ? Wv : Wp;
        float2 v = ((const float2*)src)[wi];
        ((__half2*)g_wh)[(size_t)which * WPAIRS + wi] =
            __halves2half2(__float2half_rn(v.x), __float2half_rn(v.y));
    }
}

// ---------------------------------------------------------------------------
// GEMM: C[64x128] = A * Wh^T, fp16, templated 1-term (Ah) or 2-term (Ah+Al).
// 128 threads = 4 warps (1m x 4n), warp tile 64x32, 4 CTAs/SM.
// smem: 2 stages x (Ah 64x32 [, Al 64x32], Bh 128x32) fp16, row stride 40.
// ---------------------------------------------------------------------------
#define GSTR 40
#define GA_ELEMS (64*GSTR)           // 2560 elems per A tile
#define GB_ELEMS (128*GSTR)          // 5120 elems per B tile
#define GSTAGE_B ((2*GA_ELEMS + GB_ELEMS)*2)   // 20480 bytes per stage
#define GSMEM (2*GSTAGE_B)           // 40960

template<bool LO>
__device__ __forceinline__ void gemm_issue(
    uint32_t sb, int stage,
    const __half* __restrict__ Ah, const __half* __restrict__ Al,
    const __half* __restrict__ Bh, int m0, int n0, int k0)
{
    const int t = threadIdx.x;
    const uint32_t stb = sb + stage * GSTAGE_B;
    #pragma unroll
    for (int i = 0; i < 2; i++) {
        int idx = i * 128 + t;
        int row = idx >> 2, c16 = idx & 3;
        cp16(stb + (uint32_t)(row * GSTR + c16 * 8) * 2,
             Ah + (size_t)(m0 + row) * CC + k0 + c16 * 8);
    }
    if (LO) {
        #pragma unroll
        for (int i = 0; i < 2; i++) {
            int idx = i * 128 + t;
            int row = idx >> 2, c16 = idx & 3;
            cp16(stb + (uint32_t)(GA_ELEMS + row * GSTR + c16 * 8) * 2,
                 Al + (size_t)(m0 + row) * CC + k0 + c16 * 8);
        }
    }
    #pragma unroll
    for (int i = 0; i < 4; i++) {
        int idx = i * 128 + t;
        int row = idx >> 2, c16 = idx & 3;
        cp16(stb + (uint32_t)(2 * GA_ELEMS + row * GSTR + c16 * 8) * 2,
             Bh + (size_t)(n0 + row) * CC + k0 + c16 * 8);
    }
}

template<bool LO>
__device__ __forceinline__ void gemm_body(
    const __half* __restrict__ Ah, const __half* __restrict__ Al,
    const __half* __restrict__ Bh,
    int m0, int n0, uint32_t sb, float acc[4][4][4])
{
    const int l  = threadIdx.x & 31;
    const int wn = threadIdx.x >> 5;     // 0..3

    #pragma unroll
    for (int mf = 0; mf < 4; mf++)
        #pragma unroll
        for (int nf = 0; nf < 4; nf++)
            #pragma unroll
            for (int q = 0; q < 4; q++) acc[mf][nf][q] = 0.f;

    gemm_issue<LO>(sb, 0, Ah, Al, Bh, m0, n0, 0);
    cp_commit();

    const uint32_t lrow = (l & 15);
    const uint32_t lkad = ((l >> 4) << 3);

    #pragma unroll 1
    for (int c = 0; c < 32; c++) {
        cp_wait<0>();            // chunk c landed
        __syncthreads();         // all 4 warps done with chunk c-1 -> stage free
        if (c + 1 < 32)
            gemm_issue<LO>(sb, (c + 1) & 1, Ah, Al, Bh, m0, n0, (c + 1) * 32);
        cp_commit();             // uniform group count

        const uint32_t stb = sb + (c & 1) * GSTAGE_B;
        const uint32_t tAh = stb;
        const uint32_t tAl = stb + GA_ELEMS * 2;
        const uint32_t tBh = stb + 2 * GA_ELEMS * 2;

        #pragma unroll
        for (int ks = 0; ks < 32; ks += 16) {
            uint32_t ah[4][4], al[4][4];
            #pragma unroll
            for (int mf = 0; mf < 4; mf++) {
                uint32_t off = (uint32_t)((mf * 16 + lrow) * GSTR + ks + lkad) * 2;
                ldsm4(ah[mf], tAh + off);
                if (LO) ldsm4(al[mf], tAl + off);
            }
            uint32_t bh[4][2];
            #pragma unroll
            for (int p = 0; p < 2; p++) {
                uint32_t off = (uint32_t)((wn * 32 + p * 16 + lrow) * GSTR + ks + lkad) * 2;
                uint32_t r[4];
                ldsm4(r, tBh + off);
                bh[2*p][0]   = r[0]; bh[2*p][1]   = r[2];
                bh[2*p+1][0] = r[1]; bh[2*p+1][1] = r[3];
            }
            #pragma unroll
            for (int mf = 0; mf < 4; mf++)
                #pragma unroll
                for (int nf = 0; nf < 4; nf++)
                    mma_f16(acc[mf][nf], ah[mf], bh[nf][0], bh[nf][1]);
            if (LO) {
                #pragma unroll
                for (int mf = 0; mf < 4; mf++)
                    #pragma unroll
                    for (int nf = 0; nf < 4; nf++)
                        mma_f16(acc[mf][nf], al[mf], bh[nf][0], bh[nf][1]);
            }
        }
    }
}

// Q projection (2-term): grid (8, 128). q -> hi/lo fp16 [B,H,T,D], pre-scaled.
__global__ __launch_bounds__(128, 4)
void gemm_q() {
    extern __shared__ __align__(16) char gsm[];
    const uint32_t sb = smem_u32(gsm);
    const int m0 = blockIdx.y * 64;
    const int n0 = blockIdx.x * 128;

    float acc[4][4][4];
    gemm_body<true>(g_xh, g_xl, g_wh, m0, n0, sb, acc);

    const int l  = threadIdx.x & 31;
    const int wn = threadIdx.x >> 5;

    #pragma unroll
    for (int mf = 0; mf < 4; mf++) {
        #pragma unroll
        for (int nf = 0; nf < 4; nf++) {
            int col = n0 + wn * 32 + nf * 8 + (l & 3) * 2;
            int hh = col >> 6, d = col & 63;
            #pragma unroll
            for (int hf = 0; hf < 2; hf++) {
                int m = m0 + mf * 16 + (l >> 2) + hf * 8;
                int b = m >> 11, t = m & (TT - 1);
                size_t idx = (((size_t)(b * HH + hh) * TT + t) << 6) + d;
                float f0 = acc[mf][nf][hf*2 + 0] * QSCALE;
                float f1 = acc[mf][nf][hf*2 + 1] * QSCALE;
                __half h0 = __float2half_rn(f0), h1 = __float2half_rn(f1);
                *(__half2*)&g_qh[idx] = __halves2half2(h0, h1);
                *(__half2*)&g_ql[idx] = __halves2half2(
                    __float2half_rn(f0 - __half2float(h0)),
                    __float2half_rn(f1 - __half2float(h1)));
            }
        }
    }
}

// K/V projections (1-term): grid (8, 128, 2). single fp16 out [B,H,T,D]
__global__ __launch_bounds__(128, 4)
void gemm_kv() {
    extern __shared__ __align__(16) char gsm[];
    const uint32_t sb = smem_u32(gsm);
    const int which = blockIdx.z;            // 0=K, 1=V
    const int m0 = blockIdx.y * 64;
    const int n0 = blockIdx.x * 128;
    const __half* Wh = g_wh + (size_t)(which + 1) * CC * CC;

    float acc[4][4][4];
    gemm_body<false>(g_xh, nullptr, Wh, m0, n0, sb, acc);

    __half* dst = (which == 0) ? g_kh : g_vh;
    const int l  = threadIdx.x & 31;
    const int wn = threadIdx.x >> 5;

    #pragma unroll
    for (int mf = 0; mf < 4; mf++) {
        #pragma unroll
        for (int nf = 0; nf < 4; nf++) {
            int col = n0 + wn * 32 + nf * 8 + (l & 3) * 2;
            int hh = col >> 6, d = col & 63;
            #pragma unroll
            for (int hf = 0; hf < 2; hf++) {
                int m = m0 + mf * 16 + (l >> 2) + hf * 8;
                int b = m >> 11, t = m & (TT - 1);
                size_t idx = (((size_t)(b * HH + hh) * TT + t) << 6) + d;
                *(uint32_t*)&dst[idx] = pack2(acc[mf][nf][hf*2 + 0],
                                              acc[mf][nf][hf*2 + 1]);
            }
        }
    }
}

// Output projection (1-term): grid (8, 128); fp32 out
__global__ __launch_bounds__(128, 4)
void gemm_proj(float* __restrict__ out) {
    extern __shared__ __align__(16) char gsm[];
    const uint32_t sb = smem_u32(gsm);
    const int m0 = blockIdx.y * 64;
    const int n0 = blockIdx.x * 128;
    const __half* Wh = g_wh + (size_t)3 * CC * CC;

    float acc[4][4][4];
    gemm_body<false>(g_yh, nullptr, Wh, m0, n0, sb, acc);

    const int l  = threadIdx.x & 31;
    const int wn = threadIdx.x >> 5;

    #pragma unroll
    for (int mf = 0; mf < 4; mf++)
        #pragma unroll
        for (int nf = 0; nf < 4; nf++) {
            int col = n0 + wn * 32 + nf * 8 + (l & 3) * 2;
            #pragma unroll
            for (int hf = 0; hf < 2; hf++) {
                int m = m0 + mf * 16 + (l >> 2) + hf * 8;
                *(float2*)&out[(size_t)m * CC + col] =
                    make_float2(acc[mf][nf][hf*2 + 0], acc[mf][nf][hf*2 + 1]);
            }
        }
}

// ---------------------------------------------------------------------------
// Flash attention. grid (32, 64), 128 thr (4 warps). BR=64 (16/warp), BC=64.
// Logits arrive pre-scaled in log2 domain (QSCALE folded into q) -> exp2f
// softmax, no per-tile scale multiply. QK^T 2-term; PV 1-term.
// KV 2-stage cp.async ring, 4 CTAs/SM.
// ---------------------------------------------------------------------------
#define FSTR 72
#define FKV_T (64*FSTR)              // 4608 elems per KV tile
#define FKV_STAGE_B (2*FKV_T*2)      // 18432 bytes per stage (Kh, Vh)
#define FQ_T (64*FSTR)               // 4608 elems per Q tile
#define FQ_OFF (2*FKV_STAGE_B)       // 36864
#define FSMEM (FQ_OFF + 2*FQ_T*2)    // 55296

__device__ __forceinline__ void kv_issue(uint32_t sb, int stage, size_t hb, int jt) {
    const int t = threadIdx.x;
    const uint32_t stb = sb + stage * FKV_STAGE_B;
    #pragma unroll
    for (int i = 0; i < 8; i++) {
        const int tile = i >> 2;                 // 0=K, 1=V
        int idx = ((i & 3) << 7) | t;            // 0..511
        int row = idx >> 3;
        int c16 = idx & 7;
        size_t go = hb + (size_t)(jt * 64 + row) * DD + c16 * 8;
        const __half* src = (tile == 0) ? (g_kh + go) : (g_vh + go);
        cp16(stb + (uint32_t)(tile * FKV_T + row * FSTR + c16 * 8) * 2, src);
    }
}

__global__ __launch_bounds__(128, 4)
void flash_mma() {
    extern __shared__ __align__(16) char fsm[];
    const uint32_t sb = smem_u32(fsm);

    const int tid = threadIdx.x;
    const int l   = tid & 31;
    const int w   = tid >> 5;            // 0..3
    const int qt  = (int)(gridDim.x - 1 - blockIdx.x);
    const int bh  = blockIdx.y;
    const int b   = bh >> 4;
    const int hh  = bh & 15;
    const size_t hb = (size_t)bh * TT * DD;
    const int ntile = qt + 1;

    // Q load (hi/lo) + kv0 in one group
    #pragma unroll
    for (int i = 0; i < 8; i++) {
        const int tile = i >> 2;                 // 0=hi, 1=lo
        int idx = ((i & 3) << 7) | tid;          // 0..511
        int row = idx >> 3;
        int c16 = idx & 7;
        const __half* src = (tile == 0 ? g_qh : g_ql) + hb + (size_t)(qt * 64 + row) * DD + c16 * 8;
        cp16(sb + FQ_OFF + (uint32_t)(tile * FQ_T + row * FSTR + c16 * 8) * 2, src);
    }
    kv_issue(sb, 0, hb, 0);
    cp_commit();

    float s[8][4], o[8][4];
    float m0_ = -1e30f, m1_ = -1e30f, l0_ = 0.f, l1_ = 0.f;
    #pragma unroll
    for (int nf = 0; nf < 8; nf++)
        #pragma unroll
        for (int q = 0; q < 4; q++) o[nf][q] = 0.f;

    const uint32_t sQh = sb + FQ_OFF;
    const uint32_t sQl = sQh + FQ_T * 2;
    const uint32_t lrow = (l & 15);
    const uint32_t lkad = ((l >> 4) << 3);

    #pragma unroll 1
    for (int jt = 0; jt < ntile; jt++) {
        cp_wait<0>();            // kv tile jt (and Q on jt=0) landed
        __syncthreads();         // 4 warps done with tile jt-1
        if (jt + 1 < ntile)
            kv_issue(sb, (jt + 1) & 1, hb, jt + 1);
        cp_commit();             // uniform group count

        const uint32_t kvb = sb + (jt & 1) * FKV_STAGE_B;
        const uint32_t sKh = kvb;
        const uint32_t sVh = kvb + FKV_T * 2;

        // ---- S = Q K^T (2-term, hi sweep then lo sweep) ----
        #pragma unroll
        for (int nf = 0; nf < 8; nf++)
            #pragma unroll
            for (int q = 0; q < 4; q++) s[nf][q] = 0.f;

        #pragma unroll
        for (int kd = 0; kd < 4; kd++) {
            uint32_t qh[4], ql[4];
            uint32_t offq = (uint32_t)((w * 16 + lrow) * FSTR + kd * 16 + lkad) * 2;
            ldsm4(qh, sQh + offq);
            ldsm4(ql, sQl + offq);
            uint32_t rk[4][4];
            #pragma unroll
            for (int p = 0; p < 4; p++) {
                uint32_t offk = (uint32_t)((p * 16 + lrow) * FSTR + kd * 16 + lkad) * 2;
                ldsm4(rk[p], sKh + offk);
            }
            #pragma unroll
            for (int p = 0; p < 4; p++) {
                mma_f16(s[2*p],   qh, rk[p][0], rk[p][2]);
                mma_f16(s[2*p+1], qh, rk[p][1], rk[p][3]);
            }
            #pragma unroll
            for (int p = 0; p < 4; p++) {
                mma_f16(s[2*p],   ql, rk[p][0], rk[p][2]);
                mma_f16(s[2*p+1], ql, rk[p][1], rk[p][3]);
            }
        }

        // ---- causal mask (logits already scaled, log2 domain) ----
        const int row_lo = qt * 64 + w * 16 + (l >> 2);
        const int row_hi = row_lo + 8;
        const int col0 = jt * 64 + (l & 3) * 2;
        if (jt == qt) {
            #pragma unroll
            for (int nf = 0; nf < 8; nf++) {
                int c = col0 + nf * 8;
                if (c     > row_lo) s[nf][0] = -1e30f;
                if (c + 1 > row_lo) s[nf][1] = -1e30f;
                if (c     > row_hi) s[nf][2] = -1e30f;
                if (c + 1 > row_hi) s[nf][3] = -1e30f;
            }
        }

        // ---- online softmax (base 2) ----
        float mt0 = -1e30f, mt1 = -1e30f;
        #pragma unroll
        for (int nf = 0; nf < 8; nf++) {
            mt0 = fmaxf(mt0, fmaxf(s[nf][0], s[nf][1]));
            mt1 = fmaxf(mt1, fmaxf(s[nf][2], s[nf][3]));
        }
        mt0 = fmaxf(mt0, __shfl_xor_sync(0xffffffffu, mt0, 1));
        mt0 = fmaxf(mt0, __shfl_xor_sync(0xffffffffu, mt0, 2));
        mt1 = fmaxf(mt1, __shfl_xor_sync(0xffffffffu, mt1, 1));
        mt1 = fmaxf(mt1, __shfl_xor_sync(0xffffffffu, mt1, 2));
        float mn0 = fmaxf(m0_, mt0);
        float mn1 = fmaxf(m1_, mt1);
        float cr0 = exp2f(m0_ - mn0);
        float cr1 = exp2f(m1_ - mn1);
        float rs0 = 0.f, rs1 = 0.f;
        #pragma unroll
        for (int nf = 0; nf < 8; nf++) {
            s[nf][0] = exp2f(s[nf][0] - mn0);
            s[nf][1] = exp2f(s[nf][1] - mn0);
            s[nf][2] = exp2f(s[nf][2] - mn1);
            s[nf][3] = exp2f(s[nf][3] - mn1);
            rs0 += s[nf][0] + s[nf][1];
            rs1 += s[nf][2] + s[nf][3];
        }
        rs0 += __shfl_xor_sync(0xffffffffu, rs0, 1);
        rs0 += __shfl_xor_sync(0xffffffffu, rs0, 2);
        rs1 += __shfl_xor_sync(0xffffffffu, rs1, 1);
        rs1 += __shfl_xor_sync(0xffffffffu, rs1, 2);
        l0_ = l0_ * cr0 + rs0;
        l1_ = l1_ * cr1 + rs1;
        m0_ = mn0; m1_ = mn1;
        #pragma unroll
        for (int nf = 0; nf < 8; nf++) {
            o[nf][0] *= cr0; o[nf][1] *= cr0;
            o[nf][2] *= cr1; o[nf][3] *= cr1;
        }

        // ---- P fragments (fp16, packed convert) ----
        uint32_t ph[4][4];
        #pragma unroll
        for (int kk = 0; kk < 4; kk++) {
            ph[kk][0] = pack2(s[2*kk][0],   s[2*kk][1]);
            ph[kk][1] = pack2(s[2*kk][2],   s[2*kk][3]);
            ph[kk][2] = pack2(s[2*kk+1][0], s[2*kk+1][1]);
            ph[kk][3] = pack2(s[2*kk+1][2], s[2*kk+1][3]);
        }

        // ---- O += P V (1-term) ----
        #pragma unroll
        for (int kk = 0; kk < 4; kk++) {
            #pragma unroll
            for (int p = 0; p < 4; p++) {
                uint32_t offv = (uint32_t)((kk * 16 + lrow) * FSTR + p * 16 + lkad) * 2;
                uint32_t rv[4];
                ldsm4t(rv, sVh + offv);
                mma_f16(o[2*p],   ph[kk], rv[0], rv[1]);
                mma_f16(o[2*p+1], ph[kk], rv[2], rv[3]);
            }
        }
    }

    // ---- epilogue: normalize, write y as fp16 [B,T,C] ----
    const float inv0 = 1.f / l0_;
    const float inv1 = 1.f / l1_;
    const int t0 = qt * 64 + w * 16 + (l >> 2);
    #pragma unroll
    for (int nf = 0; nf < 8; nf++) {
        int col = hh * 64 + nf * 8 + (l & 3) * 2;
        #pragma unroll
        for (int hf = 0; hf < 2; hf++) {
            int t = t0 + hf * 8;
            float inv = hf ? inv1 : inv0;
            size_t idx = ((size_t)(b * TT + t) << 10) + col;
            *(uint32_t*)&g_yh[idx] = pack2(o[nf][hf*2 + 0] * inv,
                                           o[nf][hf*2 + 1] * inv);
        }
    }
}

// ---------------------------------------------------------------------------
extern "C" void kernel_launch(void* const* d_in, const int* in_sizes, int n_in,
                              void* d_out, int out_size)
{
    const float* x  = (const float*)d_in[0];
    const float* Wq = (const float*)d_in[1];
    const float* Wk = (const float*)d_in[2];
    const float* Wv = (const float*)d_in[3];
    const float* Wp = (const float*)d_in[4];
    float* out = (float*)d_out;

    cudaFuncSetAttribute(gemm_q,    cudaFuncAttributeMaxDynamicSharedMemorySize, GSMEM);
    cudaFuncSetAttribute(gemm_kv,   cudaFuncAttributeMaxDynamicSharedMemorySize, GSMEM);
    cudaFuncSetAttribute(gemm_proj, cudaFuncAttributeMaxDynamicSharedMemorySize, GSMEM);
    cudaFuncSetAttribute(flash_mma, cudaFuncAttributeMaxDynamicSharedMemorySize, FSMEM);

    size_t total_pairs = XPAIRS + 4 * WPAIRS;   // 6M
    cvt_inputs<<<(unsigned)((total_pairs + 255) / 256), 256>>>(x, Wq, Wk, Wv, Wp);

    gemm_q<<<dim3(CC/128, MM/64), 128, GSMEM>>>();
    gemm_kv<<<dim3(CC/128, MM/64, 2), 128, GSMEM>>>();
    flash_mma<<<dim3(TT/64, BB*HH), 128, FSMEM>>>();
    gemm_proj<<<dim3(CC/128, MM/64), 128, GSMEM>>>(out);
}

// round 12
// speedup vs baseline: 9.0981x; 1.2214x over previous
#include <cuda_runtime.h>
#include <cuda_fp16.h>
#include <cstdint>

#define BB 4
#define TT 2048
#define CC 1024
#define HH 16
#define DD 64
#define MM (BB*TT)   // 8192

// logits pre-scale: 1/sqrt(D) * log2(e), folded into q at projection time
#define QSCALE 0.18033688011112042f

// ---------------------------------------------------------------------------
// Scratch (device globals, 16B aligned)
// ---------------------------------------------------------------------------
__device__ __align__(16) __half g_xh[(size_t)MM*CC];
__device__ __align__(16) __half g_wh[(size_t)4*CC*CC];   // q,k,v,p (hi only)
__device__ __align__(16) __half g_qh[(size_t)MM*CC];     // [B,H,T,D] (pre-scaled)
__device__ __align__(16) __half g_kh[(size_t)MM*CC];
__device__ __align__(16) __half g_vh[(size_t)MM*CC];
__device__ __align__(16) __half g_yh[(size_t)MM*CC];     // [B,T,C]

// ---------------------------------------------------------------------------
// PTX helpers
// ---------------------------------------------------------------------------
__device__ __forceinline__ uint32_t smem_u32(const void* p) {
    uint32_t a;
    asm("{ .reg .u64 t; cvta.to.shared.u64 t, %1; cvt.u32.u64 %0, t; }"
        : "=r"(a) : "l"(p));
    return a;
}
__device__ __forceinline__ void cp16(uint32_t dst, const void* src) {
    asm volatile("cp.async.cg.shared.global [%0], [%1], 16;" :: "r"(dst), "l"(src));
}
__device__ __forceinline__ void cp_commit() {
    asm volatile("cp.async.commit_group;" ::: "memory");
}
template<int N> __device__ __forceinline__ void cp_wait() {
    asm volatile("cp.async.wait_group %0;" :: "n"(N) : "memory");
}
__device__ __forceinline__ void ldsm4(uint32_t* r, uint32_t a) {
    asm volatile("ldmatrix.sync.aligned.m8n8.x4.shared.b16 {%0,%1,%2,%3}, [%4];"
        : "=r"(r[0]), "=r"(r[1]), "=r"(r[2]), "=r"(r[3]) : "r"(a));
}
__device__ __forceinline__ void ldsm4t(uint32_t* r, uint32_t a) {
    asm volatile("ldmatrix.sync.aligned.m8n8.x4.trans.shared.b16 {%0,%1,%2,%3}, [%4];"
        : "=r"(r[0]), "=r"(r[1]), "=r"(r[2]), "=r"(r[3]) : "r"(a));
}
__device__ __forceinline__ void mma_f16(float* d, const uint32_t* a, uint32_t b0, uint32_t b1) {
    asm volatile(
        "mma.sync.aligned.m16n8k16.row.col.f32.f16.f16.f32 "
        "{%0,%1,%2,%3}, {%4,%5,%6,%7}, {%8,%9}, {%0,%1,%2,%3};"
        : "+f"(d[0]), "+f"(d[1]), "+f"(d[2]), "+f"(d[3])
        : "r"(a[0]), "r"(a[1]), "r"(a[2]), "r"(a[3]), "r"(b0), "r"(b1));
}
__device__ __forceinline__ uint32_t pack2(float a, float b) {
    __half2 h = __float22half2_rn(make_float2(a, b));   // single F2FP.PACK
    return *(uint32_t*)&h;
}

// ---------------------------------------------------------------------------
// Fused conversion: x -> fp16, W{q,k,v,p} -> fp16. 2 elems/thread.
// ---------------------------------------------------------------------------
#define XPAIRS ((size_t)MM*CC/2)     // 4194304
#define WPAIRS ((size_t)CC*CC/2)     // 524288

__global__ void cvt_inputs(const float* __restrict__ x,
                           const float* __restrict__ Wq, const float* __restrict__ Wk,
                           const float* __restrict__ Wv, const float* __restrict__ Wp) {
    size_t i = (size_t)blockIdx.x * blockDim.x + threadIdx.x;
    if (i < XPAIRS) {
        float2 v = ((const float2*)x)[i];
        ((__half2*)g_xh)[i] = __float22half2_rn(make_float2(v.x, v.y));
    } else {
        size_t j = i - XPAIRS;
        int which = (int)(j >> 19);
        size_t wi = j & (WPAIRS - 1);
        const float* src = (which == 0) ? Wq : (which == 1) ? Wk : (which == 2) ? Wv : Wp;
        float2 v = ((const float2*)src)[wi];
        ((__half2*)g_wh)[(size_t)which * WPAIRS + wi] =
            __float22half2_rn(make_float2(v.x, v.y));
    }
}

// ---------------------------------------------------------------------------
// GEMM: C[64x128] = Ah * Wh^T, fp16 1-term.
// 128 threads = 4 warps (1m x 4n), warp tile 64x32, 4 CTAs/SM.
// smem: 2 stages x (Ah 64x32, Bh 128x32) fp16, row stride 40.
// ---------------------------------------------------------------------------
#define GSTR 40
#define GA_ELEMS (64*GSTR)           // 2560 elems per A tile
#define GB_ELEMS (128*GSTR)          // 5120 elems per B tile
#define GSTAGE_B ((GA_ELEMS + GB_ELEMS)*2)     // 15360 bytes per stage
#define GSMEM (2*GSTAGE_B)           // 30720

__device__ __forceinline__ void gemm_issue(
    uint32_t sb, int stage,
    const __half* __restrict__ Ah, const __half* __restrict__ Bh,
    int m0, int n0, int k0)
{
    const int t = threadIdx.x;
    const uint32_t stb = sb + stage * GSTAGE_B;
    #pragma unroll
    for (int i = 0; i < 2; i++) {
        int idx = i * 128 + t;
        int row = idx >> 2, c16 = idx & 3;
        cp16(stb + (uint32_t)(row * GSTR + c16 * 8) * 2,
             Ah + (size_t)(m0 + row) * CC + k0 + c16 * 8);
    }
    #pragma unroll
    for (int i = 0; i < 4; i++) {
        int idx = i * 128 + t;
        int row = idx >> 2, c16 = idx & 3;
        cp16(stb + (uint32_t)(GA_ELEMS + row * GSTR + c16 * 8) * 2,
             Bh + (size_t)(n0 + row) * CC + k0 + c16 * 8);
    }
}

__device__ __forceinline__ void gemm_body(
    const __half* __restrict__ Ah, const __half* __restrict__ Bh,
    int m0, int n0, uint32_t sb, float acc[4][4][4])
{
    const int l  = threadIdx.x & 31;
    const int wn = threadIdx.x >> 5;     // 0..3

    #pragma unroll
    for (int mf = 0; mf < 4; mf++)
        #pragma unroll
        for (int nf = 0; nf < 4; nf++)
            #pragma unroll
            for (int q = 0; q < 4; q++) acc[mf][nf][q] = 0.f;

    gemm_issue(sb, 0, Ah, Bh, m0, n0, 0);
    cp_commit();

    const uint32_t lrow = (l & 15);
    const uint32_t lkad = ((l >> 4) << 3);

    #pragma unroll 1
    for (int c = 0; c < 32; c++) {
        cp_wait<0>();            // chunk c landed
        __syncthreads();         // all 4 warps done with chunk c-1 -> stage free
        if (c + 1 < 32)
            gemm_issue(sb, (c + 1) & 1, Ah, Bh, m0, n0, (c + 1) * 32);
        cp_commit();             // uniform group count

        const uint32_t stb = sb + (c & 1) * GSTAGE_B;
        const uint32_t tAh = stb;
        const uint32_t tBh = stb + GA_ELEMS * 2;

        #pragma unroll
        for (int ks = 0; ks < 32; ks += 16) {
            uint32_t ah[4][4];
            #pragma unroll
            for (int mf = 0; mf < 4; mf++) {
                uint32_t off = (uint32_t)((mf * 16 + lrow) * GSTR + ks + lkad) * 2;
                ldsm4(ah[mf], tAh + off);
            }
            uint32_t bh[4][2];
            #pragma unroll
            for (int p = 0; p < 2; p++) {
                uint32_t off = (uint32_t)((wn * 32 + p * 16 + lrow) * GSTR + ks + lkad) * 2;
                uint32_t r[4];
                ldsm4(r, tBh + off);
                bh[2*p][0]   = r[0]; bh[2*p][1]   = r[2];
                bh[2*p+1][0] = r[1]; bh[2*p+1][1] = r[3];
            }
            #pragma unroll
            for (int mf = 0; mf < 4; mf++)
                #pragma unroll
                for (int nf = 0; nf < 4; nf++)
                    mma_f16(acc[mf][nf], ah[mf], bh[nf][0], bh[nf][1]);
        }
    }
}

// Fused QKV projection (all 1-term): grid (8, 128, 3). [B,H,T,D] fp16 out.
// q gets QSCALE folded in.
__global__ __launch_bounds__(128, 4)
void gemm_qkv() {
    extern __shared__ __align__(16) char gsm[];
    const uint32_t sb = smem_u32(gsm);
    const int which = blockIdx.z;            // 0=Q, 1=K, 2=V
    const int m0 = blockIdx.y * 64;
    const int n0 = blockIdx.x * 128;
    const __half* Wh = g_wh + (size_t)which * CC * CC;

    float acc[4][4][4];
    gemm_body(g_xh, Wh, m0, n0, sb, acc);

    __half* dst = (which == 0) ? g_qh : (which == 1) ? g_kh : g_vh;
    const float scl = (which == 0) ? QSCALE : 1.0f;
    const int l  = threadIdx.x & 31;
    const int wn = threadIdx.x >> 5;

    #pragma unroll
    for (int mf = 0; mf < 4; mf++) {
        #pragma unroll
        for (int nf = 0; nf < 4; nf++) {
            int col = n0 + wn * 32 + nf * 8 + (l & 3) * 2;
            int hh = col >> 6, d = col & 63;
            #pragma unroll
            for (int hf = 0; hf < 2; hf++) {
                int m = m0 + mf * 16 + (l >> 2) + hf * 8;
                int b = m >> 11, t = m & (TT - 1);
                size_t idx = (((size_t)(b * HH + hh) * TT + t) << 6) + d;
                *(uint32_t*)&dst[idx] = pack2(acc[mf][nf][hf*2 + 0] * scl,
                                              acc[mf][nf][hf*2 + 1] * scl);
            }
        }
    }
}

// Output projection (1-term): grid (8, 128); fp32 out
__global__ __launch_bounds__(128, 4)
void gemm_proj(float* __restrict__ out) {
    extern __shared__ __align__(16) char gsm[];
    const uint32_t sb = smem_u32(gsm);
    const int m0 = blockIdx.y * 64;
    const int n0 = blockIdx.x * 128;
    const __half* Wh = g_wh + (size_t)3 * CC * CC;

    float acc[4][4][4];
    gemm_body(g_yh, Wh, m0, n0, sb, acc);

    const int l  = threadIdx.x & 31;
    const int wn = threadIdx.x >> 5;

    #pragma unroll
    for (int mf = 0; mf < 4; mf++)
        #pragma unroll
        for (int nf = 0; nf < 4; nf++) {
            int col = n0 + wn * 32 + nf * 8 + (l & 3) * 2;
            #pragma unroll
            for (int hf = 0; hf < 2; hf++) {
                int m = m0 + mf * 16 + (l >> 2) + hf * 8;
                *(float2*)&out[(size_t)m * CC + col] =
                    make_float2(acc[mf][nf][hf*2 + 0], acc[mf][nf][hf*2 + 1]);
            }
        }
}

// ---------------------------------------------------------------------------
// Flash attention. grid (32, 64), 128 thr (4 warps). BR=64 (16/warp), BC=64.
// Logits pre-scaled in log2 domain -> exp2f softmax. QK^T 1-term; PV 1-term.
// KV 2-stage cp.async ring, 4 CTAs/SM.
// ---------------------------------------------------------------------------
#define FSTR 72
#define FKV_T (64*FSTR)              // 4608 elems per KV tile
#define FKV_STAGE_B (2*FKV_T*2)      // 18432 bytes per stage (Kh, Vh)
#define FQ_T (64*FSTR)               // 4608 elems Q tile (hi only)
#define FQ_OFF (2*FKV_STAGE_B)       // 36864
#define FSMEM (FQ_OFF + FQ_T*2)      // 46080

__device__ __forceinline__ void kv_issue(uint32_t sb, int stage, size_t hb, int jt) {
    const int t = threadIdx.x;
    const uint32_t stb = sb + stage * FKV_STAGE_B;
    #pragma unroll
    for (int i = 0; i < 8; i++) {
        const int tile = i >> 2;                 // 0=K, 1=V
        int idx = ((i & 3) << 7) | t;            // 0..511
        int row = idx >> 3;
        int c16 = idx & 7;
        size_t go = hb + (size_t)(jt * 64 + row) * DD + c16 * 8;
        const __half* src = (tile == 0) ? (g_kh + go) : (g_vh + go);
        cp16(stb + (uint32_t)(tile * FKV_T + row * FSTR + c16 * 8) * 2, src);
    }
}

__global__ __launch_bounds__(128, 4)
void flash_mma() {
    extern __shared__ __align__(16) char fsm[];
    const uint32_t sb = smem_u32(fsm);

    const int tid = threadIdx.x;
    const int l   = tid & 31;
    const int w   = tid >> 5;            // 0..3
    const int qt  = (int)(gridDim.x - 1 - blockIdx.x);
    const int bh  = blockIdx.y;
    const int b   = bh >> 4;
    const int hh  = bh & 15;
    const size_t hb = (size_t)bh * TT * DD;
    const int ntile = qt + 1;

    // Q load (hi only) + kv0 in one group
    #pragma unroll
    for (int i = 0; i < 4; i++) {
        int idx = (i << 7) | tid;                // 0..511
        int row = idx >> 3;
        int c16 = idx & 7;
        const __half* src = g_qh + hb + (size_t)(qt * 64 + row) * DD + c16 * 8;
        cp16(sb + FQ_OFF + (uint32_t)(row * FSTR + c16 * 8) * 2, src);
    }
    kv_issue(sb, 0, hb, 0);
    cp_commit();

    float s[8][4], o[8][4];
    float m0_ = -1e30f, m1_ = -1e30f, l0_ = 0.f, l1_ = 0.f;
    #pragma unroll
    for (int nf = 0; nf < 8; nf++)
        #pragma unroll
        for (int q = 0; q < 4; q++) o[nf][q] = 0.f;

    const uint32_t sQh = sb + FQ_OFF;
    const uint32_t lrow = (l & 15);
    const uint32_t lkad = ((l >> 4) << 3);

    #pragma unroll 1
    for (int jt = 0; jt < ntile; jt++) {
        cp_wait<0>();            // kv tile jt (and Q on jt=0) landed
        __syncthreads();         // 4 warps done with tile jt-1
        if (jt + 1 < ntile)
            kv_issue(sb, (jt + 1) & 1, hb, jt + 1);
        cp_commit();             // uniform group count

        const uint32_t kvb = sb + (jt & 1) * FKV_STAGE_B;
        const uint32_t sKh = kvb;
        const uint32_t sVh = kvb + FKV_T * 2;

        // ---- S = Q K^T (1-term) ----
        #pragma unroll
        for (int nf = 0; nf < 8; nf++)
            #pragma unroll
            for (int q = 0; q < 4; q++) s[nf][q] = 0.f;

        #pragma unroll
        for (int kd = 0; kd < 4; kd++) {
            uint32_t qh[4];
            uint32_t offq = (uint32_t)((w * 16 + lrow) * FSTR + kd * 16 + lkad) * 2;
            ldsm4(qh, sQh + offq);
            uint32_t rk[4][4];
            #pragma unroll
            for (int p = 0; p < 4; p++) {
                uint32_t offk = (uint32_t)((p * 16 + lrow) * FSTR + kd * 16 + lkad) * 2;
                ldsm4(rk[p], sKh + offk);
            }
            #pragma unroll
            for (int p = 0; p < 4; p++) {
                mma_f16(s[2*p],   qh, rk[p][0], rk[p][2]);
                mma_f16(s[2*p+1], qh, rk[p][1], rk[p][3]);
            }
        }

        // ---- causal mask (logits already scaled, log2 domain) ----
        const int row_lo = qt * 64 + w * 16 + (l >> 2);
        const int row_hi = row_lo + 8;
        const int col0 = jt * 64 + (l & 3) * 2;
        if (jt == qt) {
            #pragma unroll
            for (int nf = 0; nf < 8; nf++) {
                int c = col0 + nf * 8;
                if (c     > row_lo) s[nf][0] = -1e30f;
                if (c + 1 > row_lo) s[nf][1] = -1e30f;
                if (c     > row_hi) s[nf][2] = -1e30f;
                if (c + 1 > row_hi) s[nf][3] = -1e30f;
            }
        }

        // ---- online softmax (base 2) ----
        float mt0 = -1e30f, mt1 = -1e30f;
        #pragma unroll
        for (int nf = 0; nf < 8; nf++) {
            mt0 = fmaxf(mt0, fmaxf(s[nf][0], s[nf][1]));
            mt1 = fmaxf(mt1, fmaxf(s[nf][2], s[nf][3]));
        }
        mt0 = fmaxf(mt0, __shfl_xor_sync(0xffffffffu, mt0, 1));
        mt0 = fmaxf(mt0, __shfl_xor_sync(0xffffffffu, mt0, 2));
        mt1 = fmaxf(mt1, __shfl_xor_sync(0xffffffffu, mt1, 1));
        mt1 = fmaxf(mt1, __shfl_xor_sync(0xffffffffu, mt1, 2));
        float mn0 = fmaxf(m0_, mt0);
        float mn1 = fmaxf(m1_, mt1);
        float cr0 = exp2f(m0_ - mn0);
        float cr1 = exp2f(m1_ - mn1);
        float rs0 = 0.f, rs1 = 0.f;
        #pragma unroll
        for (int nf = 0; nf < 8; nf++) {
            s[nf][0] = exp2f(s[nf][0] - mn0);
            s[nf][1] = exp2f(s[nf][1] - mn0);
            s[nf][2] = exp2f(s[nf][2] - mn1);
            s[nf][3] = exp2f(s[nf][3] - mn1);
            rs0 += s[nf][0] + s[nf][1];
            rs1 += s[nf][2] + s[nf][3];
        }
        rs0 += __shfl_xor_sync(0xffffffffu, rs0, 1);
        rs0 += __shfl_xor_sync(0xffffffffu, rs0, 2);
        rs1 += __shfl_xor_sync(0xffffffffu, rs1, 1);
        rs1 += __shfl_xor_sync(0xffffffffu, rs1, 2);
        l0_ = l0_ * cr0 + rs0;
        l1_ = l1_ * cr1 + rs1;
        m0_ = mn0; m1_ = mn1;
        #pragma unroll
        for (int nf = 0; nf < 8; nf++) {
            o[nf][0] *= cr0; o[nf][1] *= cr0;
            o[nf][2] *= cr1; o[nf][3] *= cr1;
        }

        // ---- P fragments (fp16, packed convert) ----
        uint32_t ph[4][4];
        #pragma unroll
        for (int kk = 0; kk < 4; kk++) {
            ph[kk][0] = pack2(s[2*kk][0],   s[2*kk][1]);
            ph[kk][1] = pack2(s[2*kk][2],   s[2*kk][3]);
            ph[kk][2] = pack2(s[2*kk+1][0], s[2*kk+1][1]);
            ph[kk][3] = pack2(s[2*kk+1][2], s[2*kk+1][3]);
        }

        // ---- O += P V (1-term) ----
        #pragma unroll
        for (int kk = 0; kk < 4; kk++) {
            #pragma unroll
            for (int p = 0; p < 4; p++) {
                uint32_t offv = (uint32_t)((kk * 16 + lrow) * FSTR + p * 16 + lkad) * 2;
                uint32_t rv[4];
                ldsm4t(rv, sVh + offv);
                mma_f16(o[2*p],   ph[kk], rv[0], rv[1]);
                mma_f16(o[2*p+1], ph[kk], rv[2], rv[3]);
            }
        }
    }

    // ---- epilogue: normalize, write y as fp16 [B,T,C] ----
    const float inv0 = 1.f / l0_;
    const float inv1 = 1.f / l1_;
    const int t0 = qt * 64 + w * 16 + (l >> 2);
    #pragma unroll
    for (int nf = 0; nf < 8; nf++) {
        int col = hh * 64 + nf * 8 + (l & 3) * 2;
        #pragma unroll
        for (int hf = 0; hf < 2; hf++) {
            int t = t0 + hf * 8;
            float inv = hf ? inv1 : inv0;
            size_t idx = ((size_t)(b * TT + t) << 10) + col;
            *(uint32_t*)&g_yh[idx] = pack2(o[nf][hf*2 + 0] * inv,
                                           o[nf][hf*2 + 1] * inv);
        }
    }
}

// ---------------------------------------------------------------------------
extern "C" void kernel_launch(void* const* d_in, const int* in_sizes, int n_in,
                              void* d_out, int out_size)
{
    const float* x  = (const float*)d_in[0];
    const float* Wq = (const float*)d_in[1];
    const float* Wk = (const float*)d_in[2];
    const float* Wv = (const float*)d_in[3];
    const float* Wp = (const float*)d_in[4];
    float* out = (float*)d_out;

    cudaFuncSetAttribute(gemm_qkv,  cudaFuncAttributeMaxDynamicSharedMemorySize, GSMEM);
    cudaFuncSetAttribute(gemm_proj, cudaFuncAttributeMaxDynamicSharedMemorySize, GSMEM);
    cudaFuncSetAttribute(flash_mma, cudaFuncAttributeMaxDynamicSharedMemorySize, FSMEM);

    size_t total_pairs = XPAIRS + 4 * WPAIRS;   // 6M
    cvt_inputs<<<(unsigned)((total_pairs + 255) / 256), 256>>>(x, Wq, Wk, Wv, Wp);

    gemm_qkv<<<dim3(CC/128, MM/64, 3), 128, GSMEM>>>();
    flash_mma<<<dim3(TT/64, BB*HH), 128, FSMEM>>>();
    gemm_proj<<<dim3(CC/128, MM/64), 128, GSMEM>>>(out);
}